// round 12
// baseline (speedup 1.0000x reference)
#include <cuda_runtime.h>
#include <cuda_fp16.h>
#include <cuda_bf16.h>
#include <cstdint>

#define NN 100000
#define DD 128
#define GG 64

// Scratch (__device__ globals; no allocation allowed)
__device__ __align__(16) __half g_xh[NN * DD];     // x * cs, fp16
__device__ __align__(16) __half g_h0[NN * DD];     // layer outputs (fp16)
__device__ __align__(16) __half g_h1[NN * DD];
__device__ __align__(16) __half g_h2[NN * DD];
__device__ __align__(16) __half g_agg[NN * DD];    // gathered+cd-scaled rows (fp16)
__device__ __align__(16) __half g_wt[3 * DD * DD]; // W transposed + fp16: wt[l][n][k]
__device__ float g_cs[NN];
__device__ float g_cd[NN];
__device__ int   g_degout[NN];
__device__ int   g_degin[NN];
__device__ int   g_rowstart[NN];
__device__ int   g_cursor[NN];                     // seeded to rowstart; atomic bump = slot
__device__ int   g_csr[1700000];
__device__ __align__(16) float g_sums[GG * DD];
__device__ float g_cnt[GG];

// ---------------------------------------------------------------------------
// Setup: zero int arrays + pool accumulators, prep all 3 W (transpose + fp16)
// ---------------------------------------------------------------------------
__global__ void setup_kernel(const float* __restrict__ W0, const float* __restrict__ W1,
                             const float* __restrict__ W2, int n) {
    int i = blockIdx.x * blockDim.x + threadIdx.x;
    if (i < n) { g_degout[i] = 0; g_degin[i] = 0; }
    if (i < 3 * DD * DD) {
        const float* W = (i < DD * DD) ? W0 : ((i < 2 * DD * DD) ? W1 : W2);
        int j = i & (DD * DD - 1);
        int k = j >> 7, nn = j & 127;
        g_wt[(i >> 14) * DD * DD + nn * DD + k] = __float2half(W[j]);
    }
    if (i < GG * DD) g_sums[i] = 0.0f;
    if (i < GG) g_cnt[i] = 0.0f;
}

__global__ void count_deg_kernel(const int* __restrict__ src,
                                 const int* __restrict__ dst, int e) {
    int i = blockIdx.x * blockDim.x + threadIdx.x;
    if (i < e) {
        atomicAdd(&g_degout[src[i]], 1);
        atomicAdd(&g_degin[dst[i]], 1);
    }
}

// Single-CTA scan over degin -> rowstart (+cursor=rowstart), plus norms.
__global__ void norm_scan_kernel(int n) {
    __shared__ int s[1024];
    int t = threadIdx.x;
    int chunk = (n + 1023) >> 10;
    int lo = min(t * chunk, n), hi = min(lo + chunk, n);
    int sum = 0;
    for (int i = lo; i < hi; i++) sum += g_degin[i];
    s[t] = sum;
    __syncthreads();
#pragma unroll
    for (int off = 1; off < 1024; off <<= 1) {
        int add = (t >= off) ? s[t - off] : 0;
        __syncthreads();
        s[t] += add;
        __syncthreads();
    }
    int run = s[t] - sum;   // exclusive
    for (int i = lo; i < hi; i++) {
        g_rowstart[i] = run;
        g_cursor[i] = run;           // cursor doubles as the write position
        run += g_degin[i];
    }
    for (int i = t; i < n; i += 1024) {
        g_cs[i] = rsqrtf((float)(g_degout[i] + 1));
        g_cd[i] = rsqrtf((float)(g_degin[i] + 1));
    }
}

// Single atomic gives the final slot directly (cursor pre-seeded with rowstart)
__global__ void fill_csr_kernel(const int* __restrict__ src,
                                const int* __restrict__ dst, int e) {
    int i = blockIdx.x * blockDim.x + threadIdx.x;
    if (i < e) {
        int pos = atomicAdd(&g_cursor[dst[i]], 1);
        g_csr[pos] = src[i];
    }
}

// xh[node] = half(x[node] * cs[node]); one thread per float4 quad
__global__ void prep_x_kernel(const float* __restrict__ x, int n) {
    int i = blockIdx.x * blockDim.x + threadIdx.x;
    if (i >= n * 32) return;
    int node = i >> 5, q = i & 31;
    float c = g_cs[node];
    float4 v = __ldg((const float4*)x + (size_t)node * 32 + q);
    uint2 o;
    *(__half2*)&o.x = __float22half2_rn(make_float2(v.x * c, v.y * c));
    *(__half2*)&o.y = __float22half2_rn(make_float2(v.z * c, v.w * c));
    ((uint2*)g_xh)[(size_t)node * 32 + q] = o;
}

// ---------------------------------------------------------------------------
// Gather: agg[node] = half( cd[node] * ( hs[node] + sum_in hs[src] ) )
// TWO WARPS PER NODE: warp (node, hf) owns the 128B half-row hf (features
// 64*hf..64*hf+63). Each edge is exactly ONE warp-wide single-line 128B LDG
// (no within-LDG multi-line replays), per-warp state is small (~28 regs ->
// full 64-warp/SM occupancy), and per-warp edge-loop tails halve.
// ---------------------------------------------------------------------------
__global__ void __launch_bounds__(256)
gather_kernel(const __half* __restrict__ h, int n) {
    int w = (blockIdx.x * blockDim.x + threadIdx.x) >> 5;
    int lane = threadIdx.x & 31;
    int node = w >> 1;
    int hf = w & 1;
    if (node >= n) return;
    int base = g_rowstart[node];
    int deg  = g_degin[node];
    int off = hf * 32;   // u32 offset of this half-row within the 64-u32 row

    uint32_t a0 = __ldg((const uint32_t*)(h + (size_t)node * DD) + off + lane);
    float2 acc = __half22float2(*(__half2*)&a0);

    for (int j0 = 0; j0 < deg; j0 += 32) {
        int cnt = min(32, deg - j0);
        int sj = (lane < cnt) ? __ldg(&g_csr[base + j0 + lane]) : 0;
        int k = 0;
        for (; k + 8 <= cnt; k += 8) {
            int s[8];
#pragma unroll
            for (int u = 0; u < 8; u++) s[u] = __shfl_sync(0xffffffffu, sj, k + u);
            uint32_t v[8];
#pragma unroll
            for (int u = 0; u < 8; u++)
                v[u] = __ldg((const uint32_t*)(h + (size_t)s[u] * DD) + off + lane);
#pragma unroll
            for (int u = 0; u < 8; u++) {
                float2 b = __half22float2(*(__half2*)&v[u]);
                acc.x += b.x; acc.y += b.y;
            }
        }
        for (; k < cnt; k++) {
            int s0 = __shfl_sync(0xffffffffu, sj, k);
            uint32_t u0 = __ldg((const uint32_t*)(h + (size_t)s0 * DD) + off + lane);
            float2 b = __half22float2(*(__half2*)&u0);
            acc.x += b.x; acc.y += b.y;
        }
    }

    float cdv = g_cd[node];
    uint32_t o0;
    *(__half2*)&o0 = __float22half2_rn(make_float2(acc.x * cdv, acc.y * cdv));
    ((uint32_t*)(g_agg + (size_t)node * DD))[off + lane] = o0;
}

// ---------------------------------------------------------------------------
// Tensor-core GEMM, fp16 inputs / fp32 accum (mma.sync m16n8k16).
// out = half( relu(agg @ W + b) [* cs[row]] ). One CTA per 128 rows, 8 warps
// each 32(M)x64(N). Smem stride 136 halfs -> conflict-free fragment loads.
// ---------------------------------------------------------------------------
#define ASTR 136
#define GT_SMEM (2 * 128 * ASTR * 2)

__global__ void __launch_bounds__(256, 1)
gemm_mma_kernel(const __half* __restrict__ wt, const float* __restrict__ b,
                __half* __restrict__ out, int n, int cs_out) {
    extern __shared__ __half sh[];
    __half* Bsm = sh;               // 128 x ASTR : Wt[n][k]
    __half* Asm = sh + 128 * ASTR;  // 128 x ASTR : A[m][k]

    int t = threadIdx.x;
    int rows0 = blockIdx.x * 128;

#pragma unroll
    for (int it = 0; it < 8; it++) {
        int idx = t + it * 256;
        int r = idx >> 4, c = idx & 15;
        *(uint4*)&Bsm[r * ASTR + c * 8] = __ldg((const uint4*)wt + idx);
    }
#pragma unroll
    for (int it = 0; it < 8; it++) {
        int idx = t + it * 256;
        int r = idx >> 4, c = idx & 15;
        int gr = rows0 + r;
        if (gr > n - 1) gr = n - 1;
        *(uint4*)&Asm[r * ASTR + c * 8] = __ldg((const uint4*)(g_agg + (size_t)gr * DD) + c);
    }
    __syncthreads();

    int wid = t >> 5, lane = t & 31;
    int groupID = lane >> 2, ktid = lane & 3;
    int warpM = (wid & 3) * 32;
    int warpN = (wid >> 2) * 64;

    float acc[2][8][4];
#pragma unroll
    for (int mt = 0; mt < 2; mt++)
#pragma unroll
        for (int nt = 0; nt < 8; nt++)
#pragma unroll
            for (int q = 0; q < 4; q++) acc[mt][nt][q] = 0.0f;

#pragma unroll
    for (int k0 = 0; k0 < 128; k0 += 16) {
        uint32_t a[2][4];
#pragma unroll
        for (int mt = 0; mt < 2; mt++) {
            int r0 = warpM + mt * 16 + groupID;
            a[mt][0] = *(const uint32_t*)&Asm[r0 * ASTR + k0 + ktid * 2];
            a[mt][1] = *(const uint32_t*)&Asm[(r0 + 8) * ASTR + k0 + ktid * 2];
            a[mt][2] = *(const uint32_t*)&Asm[r0 * ASTR + k0 + ktid * 2 + 8];
            a[mt][3] = *(const uint32_t*)&Asm[(r0 + 8) * ASTR + k0 + ktid * 2 + 8];
        }
#pragma unroll
        for (int nt = 0; nt < 8; nt++) {
            int c0 = warpN + nt * 8 + groupID;
            uint32_t b0 = *(const uint32_t*)&Bsm[c0 * ASTR + k0 + ktid * 2];
            uint32_t b1 = *(const uint32_t*)&Bsm[c0 * ASTR + k0 + ktid * 2 + 8];
#pragma unroll
            for (int mt = 0; mt < 2; mt++) {
                asm volatile(
                    "mma.sync.aligned.m16n8k16.row.col.f32.f16.f16.f32 "
                    "{%0,%1,%2,%3}, {%4,%5,%6,%7}, {%8,%9}, {%0,%1,%2,%3};"
                    : "+f"(acc[mt][nt][0]), "+f"(acc[mt][nt][1]),
                      "+f"(acc[mt][nt][2]), "+f"(acc[mt][nt][3])
                    : "r"(a[mt][0]), "r"(a[mt][1]), "r"(a[mt][2]), "r"(a[mt][3]),
                      "r"(b0), "r"(b1));
            }
        }
    }

#pragma unroll
    for (int mt = 0; mt < 2; mt++) {
        int r0 = rows0 + warpM + mt * 16 + groupID;
        int r1 = r0 + 8;
        float sc0 = 1.0f, sc1 = 1.0f;
        if (cs_out) {
            if (r0 < n) sc0 = g_cs[r0];
            if (r1 < n) sc1 = g_cs[r1];
        }
#pragma unroll
        for (int nt = 0; nt < 8; nt++) {
            int col = warpN + nt * 8 + 2 * ktid;
            float2 bb = __ldg((const float2*)(b + col));
            if (r0 < n) {
                float2 o = make_float2(fmaxf(acc[mt][nt][0] + bb.x, 0.0f) * sc0,
                                       fmaxf(acc[mt][nt][1] + bb.y, 0.0f) * sc0);
                *(__half2*)(out + (size_t)r0 * DD + col) = __float22half2_rn(o);
            }
            if (r1 < n) {
                float2 o = make_float2(fmaxf(acc[mt][nt][2] + bb.x, 0.0f) * sc1,
                                       fmaxf(acc[mt][nt][3] + bb.y, 0.0f) * sc1);
                *(__half2*)(out + (size_t)r1 * DD + col) = __float22half2_rn(o);
            }
        }
    }
}

// ---------------------------------------------------------------------------
// Pooling: graph_ids sorted -> run-based accumulation, flush per run.
// ---------------------------------------------------------------------------
__global__ void pool_kernel(const __half* __restrict__ h,
                            const int* __restrict__ gid, int n) {
    int w = (blockIdx.x * blockDim.x + threadIdx.x) >> 5;
    int lane = threadIdx.x & 31;
    int n0 = w * 16;
    if (n0 >= n) return;
    int n1 = min(n0 + 16, n);

    float4 acc = make_float4(0.f, 0.f, 0.f, 0.f);
    int curg = gid[n0];
    int cnt = 0;
    for (int node = n0; node < n1; node++) {
        int g = gid[node];
        if (g != curg) {
            float* o = g_sums + curg * DD + lane * 4;
            asm volatile("red.global.add.v4.f32 [%0], {%1, %2, %3, %4};"
                         :: "l"(o), "f"(acc.x), "f"(acc.y), "f"(acc.z), "f"(acc.w)
                         : "memory");
            if (lane == 0) atomicAdd(&g_cnt[curg], (float)cnt);
            acc = make_float4(0.f, 0.f, 0.f, 0.f);
            curg = g; cnt = 0;
        }
        uint2 v = __ldg((const uint2*)h + (size_t)node * 32 + lane);
        float2 a0 = __half22float2(*(__half2*)&v.x);
        float2 a1 = __half22float2(*(__half2*)&v.y);
        acc.x += a0.x; acc.y += a0.y; acc.z += a1.x; acc.w += a1.y;
        cnt++;
    }
    float* o = g_sums + curg * DD + lane * 4;
    asm volatile("red.global.add.v4.f32 [%0], {%1, %2, %3, %4};"
                 :: "l"(o), "f"(acc.x), "f"(acc.y), "f"(acc.z), "f"(acc.w)
                 : "memory");
    if (lane == 0) atomicAdd(&g_cnt[curg], (float)cnt);
}

__global__ void divide_kernel(float* __restrict__ out) {
    int i = blockIdx.x * blockDim.x + threadIdx.x;
    if (i < GG * DD) out[i] = g_sums[i] / fmaxf(g_cnt[i >> 7], 1.0f);
}

// ---------------------------------------------------------------------------
extern "C" void kernel_launch(void* const* d_in, const int* in_sizes, int n_in,
                              void* d_out, int out_size) {
    const float* x  = (const float*)d_in[0];
    const float* Ws[3] = {(const float*)d_in[1], (const float*)d_in[3], (const float*)d_in[5]};
    const float* bs[3] = {(const float*)d_in[2], (const float*)d_in[4], (const float*)d_in[6]};
    const int* src = (const int*)d_in[7];
    const int* dst = (const int*)d_in[8];
    const int* gid = (const int*)d_in[9];

    int n = in_sizes[0] / DD;          // 100000
    int e = in_sizes[7];               // 1600000

    cudaFuncSetAttribute(gemm_mma_kernel,
                         cudaFuncAttributeMaxDynamicSharedMemorySize, GT_SMEM);

    void* pxh; cudaGetSymbolAddress(&pxh, g_xh);
    void* p0;  cudaGetSymbolAddress(&p0, g_h0);
    void* p1;  cudaGetSymbolAddress(&p1, g_h1);
    void* p2;  cudaGetSymbolAddress(&p2, g_h2);
    void* pw;  cudaGetSymbolAddress(&pw, g_wt);
    __half* xh = (__half*)pxh;
    __half* h0 = (__half*)p0;
    __half* h1 = (__half*)p1;
    __half* h2 = (__half*)p2;
    __half* wt = (__half*)pw;

    setup_kernel<<<(n + 255) / 256, 256>>>(Ws[0], Ws[1], Ws[2], n);
    count_deg_kernel<<<(e + 255) / 256, 256>>>(src, dst, e);
    norm_scan_kernel<<<1, 1024>>>(n);
    fill_csr_kernel<<<(e + 255) / 256, 256>>>(src, dst, e);
    prep_x_kernel<<<(int)(((size_t)n * 32 + 255) / 256), 256>>>(x, n);

    int gtiles = (n + 127) / 128;
    int gblocks = (int)(((size_t)n * 64 + 255) / 256);   // 2 warps per node

    gather_kernel<<<gblocks, 256>>>(xh, n);
    gemm_mma_kernel<<<gtiles, 256, GT_SMEM>>>(wt, bs[0], h0, n, 1);
    gather_kernel<<<gblocks, 256>>>(h0, n);
    gemm_mma_kernel<<<gtiles, 256, GT_SMEM>>>(wt + DD * DD, bs[1], h1, n, 1);
    gather_kernel<<<gblocks, 256>>>(h1, n);
    gemm_mma_kernel<<<gtiles, 256, GT_SMEM>>>(wt + 2 * DD * DD, bs[2], h2, n, 0);

    pool_kernel<<<(n + 127) / 128, 256>>>(h2, gid, n);
    divide_kernel<<<(GG * DD + 255) / 256, 256>>>((float*)d_out);
}

// round 13
// speedup vs baseline: 1.1082x; 1.1082x over previous
#include <cuda_runtime.h>
#include <cuda_fp16.h>
#include <cuda_bf16.h>
#include <cstdint>

#define NN 100000
#define DD 128
#define GG 64
#define NB 64   // degree buckets (clamped)

// Scratch (__device__ globals; no allocation allowed)
__device__ __align__(16) __half g_xh[NN * DD];     // x * cs, fp16
__device__ __align__(16) __half g_h0[NN * DD];     // layer outputs (fp16)
__device__ __align__(16) __half g_h1[NN * DD];
__device__ __align__(16) __half g_h2[NN * DD];
__device__ __align__(16) __half g_agg[NN * DD];    // gathered+cd-scaled rows (fp16)
__device__ __align__(16) __half g_wt[3 * DD * DD]; // W transposed + fp16: wt[l][n][k]
__device__ float g_cs[NN];
__device__ float g_cd[NN];
__device__ int   g_degout[NN];
__device__ int   g_degin[NN];
__device__ int   g_rowstart[NN];
__device__ int   g_cursor[NN];                     // seeded to rowstart; atomic bump = slot
__device__ int   g_csr[1700000];
__device__ int   g_order[NN];                      // nodes sorted by degree (desc)
__device__ int   g_bcur[NB];                       // bucket cursors
__device__ __align__(16) float g_sums[GG * DD];
__device__ float g_cnt[GG];

// ---------------------------------------------------------------------------
// Setup: zero int arrays + pool accumulators, prep all 3 W (transpose + fp16)
// ---------------------------------------------------------------------------
__global__ void setup_kernel(const float* __restrict__ W0, const float* __restrict__ W1,
                             const float* __restrict__ W2, int n) {
    int i = blockIdx.x * blockDim.x + threadIdx.x;
    if (i < n) { g_degout[i] = 0; g_degin[i] = 0; }
    if (i < 3 * DD * DD) {
        const float* W = (i < DD * DD) ? W0 : ((i < 2 * DD * DD) ? W1 : W2);
        int j = i & (DD * DD - 1);
        int k = j >> 7, nn = j & 127;
        g_wt[(i >> 14) * DD * DD + nn * DD + k] = __float2half(W[j]);
    }
    if (i < GG * DD) g_sums[i] = 0.0f;
    if (i < GG) g_cnt[i] = 0.0f;
}

__global__ void count_deg_kernel(const int* __restrict__ src,
                                 const int* __restrict__ dst, int e) {
    int i = blockIdx.x * blockDim.x + threadIdx.x;
    if (i < e) {
        atomicAdd(&g_degout[src[i]], 1);
        atomicAdd(&g_degin[dst[i]], 1);
    }
}

// Single-CTA: scan degin -> rowstart/cursor, norms, and degree-bucket offsets
// (descending counting sort setup).
__global__ void norm_scan_kernel(int n) {
    __shared__ int s[1024];
    __shared__ int hist[NB];
    int t = threadIdx.x;
    if (t < NB) hist[t] = 0;
    __syncthreads();

    int chunk = (n + 1023) >> 10;
    int lo = min(t * chunk, n), hi = min(lo + chunk, n);
    int sum = 0;
    for (int i = lo; i < hi; i++) {
        int d = g_degin[i];
        sum += d;
        atomicAdd(&hist[min(d, NB - 1)], 1);
    }
    s[t] = sum;
    __syncthreads();
#pragma unroll
    for (int off = 1; off < 1024; off <<= 1) {
        int add = (t >= off) ? s[t - off] : 0;
        __syncthreads();
        s[t] += add;
        __syncthreads();
    }
    int run = s[t] - sum;   // exclusive
    for (int i = lo; i < hi; i++) {
        g_rowstart[i] = run;
        g_cursor[i] = run;           // cursor doubles as the write position
        run += g_degin[i];
    }
    for (int i = t; i < n; i += 1024) {
        g_cs[i] = rsqrtf((float)(g_degout[i] + 1));
        g_cd[i] = rsqrtf((float)(g_degin[i] + 1));
    }
    __syncthreads();
    // Descending bucket offsets: bucket b starts after all buckets > b
    if (t == 0) {
        int off = 0;
        for (int b = NB - 1; b >= 0; b--) {
            g_bcur[b] = off;
            off += hist[b];
        }
    }
}

// Scatter node ids into degree-sorted order (desc). Nondeterministic within a
// bucket, but each node appears exactly once -> per-node results unchanged.
__global__ void order_kernel(int n) {
    int i = blockIdx.x * blockDim.x + threadIdx.x;
    if (i < n) {
        int b = min(g_degin[i], NB - 1);
        int pos = atomicAdd(&g_bcur[b], 1);
        g_order[pos] = i;
    }
}

// Single atomic gives the final slot directly (cursor pre-seeded with rowstart)
__global__ void fill_csr_kernel(const int* __restrict__ src,
                                const int* __restrict__ dst, int e) {
    int i = blockIdx.x * blockDim.x + threadIdx.x;
    if (i < e) {
        int pos = atomicAdd(&g_cursor[dst[i]], 1);
        g_csr[pos] = src[i];
    }
}

// xh[node] = half(x[node] * cs[node]); one thread per float4 quad
__global__ void prep_x_kernel(const float* __restrict__ x, int n) {
    int i = blockIdx.x * blockDim.x + threadIdx.x;
    if (i >= n * 32) return;
    int node = i >> 5, q = i & 31;
    float c = g_cs[node];
    float4 v = __ldg((const float4*)x + (size_t)node * 32 + q);
    uint2 o;
    *(__half2*)&o.x = __float22half2_rn(make_float2(v.x * c, v.y * c));
    *(__half2*)&o.y = __float22half2_rn(make_float2(v.z * c, v.w * c));
    ((uint2*)g_xh)[(size_t)node * 32 + q] = o;
}

// ---------------------------------------------------------------------------
// Gather: agg[node] = half( cd[node] * ( hs[node] + sum_in hs[src] ) )
// One warp per node, nodes taken in degree-sorted order so all warps of a CTA
// have near-equal work (CTA makespan ~= mean, not max-of-8). Each 256B row is
// read with two single-line 128B LDGs (no within-LDG multi-line replays).
// ---------------------------------------------------------------------------
__global__ void __launch_bounds__(256)
gather_kernel(const __half* __restrict__ h, int n) {
    int w = (blockIdx.x * blockDim.x + threadIdx.x) >> 5;
    int lane = threadIdx.x & 31;
    if (w >= n) return;
    int node = __ldg(&g_order[w]);
    int base = g_rowstart[node];
    int deg  = g_degin[node];

    const uint32_t* selfrow = (const uint32_t*)(h + (size_t)node * DD);
    uint32_t a0 = __ldg(selfrow + lane);
    uint32_t a1 = __ldg(selfrow + 32 + lane);
    float2 f0 = __half22float2(*(__half2*)&a0);
    float2 f1 = __half22float2(*(__half2*)&a1);
    float4 acc = make_float4(f0.x, f0.y, f1.x, f1.y);

    for (int j0 = 0; j0 < deg; j0 += 32) {
        int cnt = min(32, deg - j0);
        int sj = (lane < cnt) ? __ldg(&g_csr[base + j0 + lane]) : 0;
        int k = 0;
        for (; k + 8 <= cnt; k += 8) {
            int s[8];
#pragma unroll
            for (int u = 0; u < 8; u++) s[u] = __shfl_sync(0xffffffffu, sj, k + u);
            uint32_t v0[8], v1[8];
#pragma unroll
            for (int u = 0; u < 8; u++) {
                const uint32_t* rp = (const uint32_t*)(h + (size_t)s[u] * DD);
                v0[u] = __ldg(rp + lane);        // line 0 of the row
                v1[u] = __ldg(rp + 32 + lane);   // line 1 of the row
            }
#pragma unroll
            for (int u = 0; u < 8; u++) {
                float2 b0 = __half22float2(*(__half2*)&v0[u]);
                float2 b1 = __half22float2(*(__half2*)&v1[u]);
                acc.x += b0.x; acc.y += b0.y; acc.z += b1.x; acc.w += b1.y;
            }
        }
        for (; k < cnt; k++) {
            int s0 = __shfl_sync(0xffffffffu, sj, k);
            const uint32_t* rp = (const uint32_t*)(h + (size_t)s0 * DD);
            uint32_t u0 = __ldg(rp + lane);
            uint32_t u1 = __ldg(rp + 32 + lane);
            float2 b0 = __half22float2(*(__half2*)&u0);
            float2 b1 = __half22float2(*(__half2*)&u1);
            acc.x += b0.x; acc.y += b0.y; acc.z += b1.x; acc.w += b1.y;
        }
    }

    float cdv = g_cd[node];
    uint32_t o0, o1;
    *(__half2*)&o0 = __float22half2_rn(make_float2(acc.x * cdv, acc.y * cdv));
    *(__half2*)&o1 = __float22half2_rn(make_float2(acc.z * cdv, acc.w * cdv));
    uint32_t* orow = (uint32_t*)(g_agg + (size_t)node * DD);
    orow[lane] = o0;
    orow[32 + lane] = o1;
}

// ---------------------------------------------------------------------------
// Tensor-core GEMM, fp16 inputs / fp32 accum (mma.sync m16n8k16).
// out = half( relu(agg @ W + b) [* cs[row]] ). One CTA per 128 rows, 8 warps
// each 32(M)x64(N). Smem stride 136 halfs -> conflict-free fragment loads.
// ---------------------------------------------------------------------------
#define ASTR 136
#define GT_SMEM (2 * 128 * ASTR * 2)

__global__ void __launch_bounds__(256, 1)
gemm_mma_kernel(const __half* __restrict__ wt, const float* __restrict__ b,
                __half* __restrict__ out, int n, int cs_out) {
    extern __shared__ __half sh[];
    __half* Bsm = sh;               // 128 x ASTR : Wt[n][k]
    __half* Asm = sh + 128 * ASTR;  // 128 x ASTR : A[m][k]

    int t = threadIdx.x;
    int rows0 = blockIdx.x * 128;

#pragma unroll
    for (int it = 0; it < 8; it++) {
        int idx = t + it * 256;
        int r = idx >> 4, c = idx & 15;
        *(uint4*)&Bsm[r * ASTR + c * 8] = __ldg((const uint4*)wt + idx);
    }
#pragma unroll
    for (int it = 0; it < 8; it++) {
        int idx = t + it * 256;
        int r = idx >> 4, c = idx & 15;
        int gr = rows0 + r;
        if (gr > n - 1) gr = n - 1;
        *(uint4*)&Asm[r * ASTR + c * 8] = __ldg((const uint4*)(g_agg + (size_t)gr * DD) + c);
    }
    __syncthreads();

    int wid = t >> 5, lane = t & 31;
    int groupID = lane >> 2, ktid = lane & 3;
    int warpM = (wid & 3) * 32;
    int warpN = (wid >> 2) * 64;

    float acc[2][8][4];
#pragma unroll
    for (int mt = 0; mt < 2; mt++)
#pragma unroll
        for (int nt = 0; nt < 8; nt++)
#pragma unroll
            for (int q = 0; q < 4; q++) acc[mt][nt][q] = 0.0f;

#pragma unroll
    for (int k0 = 0; k0 < 128; k0 += 16) {
        uint32_t a[2][4];
#pragma unroll
        for (int mt = 0; mt < 2; mt++) {
            int r0 = warpM + mt * 16 + groupID;
            a[mt][0] = *(const uint32_t*)&Asm[r0 * ASTR + k0 + ktid * 2];
            a[mt][1] = *(const uint32_t*)&Asm[(r0 + 8) * ASTR + k0 + ktid * 2];
            a[mt][2] = *(const uint32_t*)&Asm[r0 * ASTR + k0 + ktid * 2 + 8];
            a[mt][3] = *(const uint32_t*)&Asm[(r0 + 8) * ASTR + k0 + ktid * 2 + 8];
        }
#pragma unroll
        for (int nt = 0; nt < 8; nt++) {
            int c0 = warpN + nt * 8 + groupID;
            uint32_t b0 = *(const uint32_t*)&Bsm[c0 * ASTR + k0 + ktid * 2];
            uint32_t b1 = *(const uint32_t*)&Bsm[c0 * ASTR + k0 + ktid * 2 + 8];
#pragma unroll
            for (int mt = 0; mt < 2; mt++) {
                asm volatile(
                    "mma.sync.aligned.m16n8k16.row.col.f32.f16.f16.f32 "
                    "{%0,%1,%2,%3}, {%4,%5,%6,%7}, {%8,%9}, {%0,%1,%2,%3};"
                    : "+f"(acc[mt][nt][0]), "+f"(acc[mt][nt][1]),
                      "+f"(acc[mt][nt][2]), "+f"(acc[mt][nt][3])
                    : "r"(a[mt][0]), "r"(a[mt][1]), "r"(a[mt][2]), "r"(a[mt][3]),
                      "r"(b0), "r"(b1));
            }
        }
    }

#pragma unroll
    for (int mt = 0; mt < 2; mt++) {
        int r0 = rows0 + warpM + mt * 16 + groupID;
        int r1 = r0 + 8;
        float sc0 = 1.0f, sc1 = 1.0f;
        if (cs_out) {
            if (r0 < n) sc0 = g_cs[r0];
            if (r1 < n) sc1 = g_cs[r1];
        }
#pragma unroll
        for (int nt = 0; nt < 8; nt++) {
            int col = warpN + nt * 8 + 2 * ktid;
            float2 bb = __ldg((const float2*)(b + col));
            if (r0 < n) {
                float2 o = make_float2(fmaxf(acc[mt][nt][0] + bb.x, 0.0f) * sc0,
                                       fmaxf(acc[mt][nt][1] + bb.y, 0.0f) * sc0);
                *(__half2*)(out + (size_t)r0 * DD + col) = __float22half2_rn(o);
            }
            if (r1 < n) {
                float2 o = make_float2(fmaxf(acc[mt][nt][2] + bb.x, 0.0f) * sc1,
                                       fmaxf(acc[mt][nt][3] + bb.y, 0.0f) * sc1);
                *(__half2*)(out + (size_t)r1 * DD + col) = __float22half2_rn(o);
            }
        }
    }
}

// ---------------------------------------------------------------------------
// Pooling: graph_ids sorted -> run-based accumulation, flush per run.
// ---------------------------------------------------------------------------
__global__ void pool_kernel(const __half* __restrict__ h,
                            const int* __restrict__ gid, int n) {
    int w = (blockIdx.x * blockDim.x + threadIdx.x) >> 5;
    int lane = threadIdx.x & 31;
    int n0 = w * 16;
    if (n0 >= n) return;
    int n1 = min(n0 + 16, n);

    float4 acc = make_float4(0.f, 0.f, 0.f, 0.f);
    int curg = gid[n0];
    int cnt = 0;
    for (int node = n0; node < n1; node++) {
        int g = gid[node];
        if (g != curg) {
            float* o = g_sums + curg * DD + lane * 4;
            asm volatile("red.global.add.v4.f32 [%0], {%1, %2, %3, %4};"
                         :: "l"(o), "f"(acc.x), "f"(acc.y), "f"(acc.z), "f"(acc.w)
                         : "memory");
            if (lane == 0) atomicAdd(&g_cnt[curg], (float)cnt);
            acc = make_float4(0.f, 0.f, 0.f, 0.f);
            curg = g; cnt = 0;
        }
        uint2 v = __ldg((const uint2*)h + (size_t)node * 32 + lane);
        float2 a0 = __half22float2(*(__half2*)&v.x);
        float2 a1 = __half22float2(*(__half2*)&v.y);
        acc.x += a0.x; acc.y += a0.y; acc.z += a1.x; acc.w += a1.y;
        cnt++;
    }
    float* o = g_sums + curg * DD + lane * 4;
    asm volatile("red.global.add.v4.f32 [%0], {%1, %2, %3, %4};"
                 :: "l"(o), "f"(acc.x), "f"(acc.y), "f"(acc.z), "f"(acc.w)
                 : "memory");
    if (lane == 0) atomicAdd(&g_cnt[curg], (float)cnt);
}

__global__ void divide_kernel(float* __restrict__ out) {
    int i = blockIdx.x * blockDim.x + threadIdx.x;
    if (i < GG * DD) out[i] = g_sums[i] / fmaxf(g_cnt[i >> 7], 1.0f);
}

// ---------------------------------------------------------------------------
extern "C" void kernel_launch(void* const* d_in, const int* in_sizes, int n_in,
                              void* d_out, int out_size) {
    const float* x  = (const float*)d_in[0];
    const float* Ws[3] = {(const float*)d_in[1], (const float*)d_in[3], (const float*)d_in[5]};
    const float* bs[3] = {(const float*)d_in[2], (const float*)d_in[4], (const float*)d_in[6]};
    const int* src = (const int*)d_in[7];
    const int* dst = (const int*)d_in[8];
    const int* gid = (const int*)d_in[9];

    int n = in_sizes[0] / DD;          // 100000
    int e = in_sizes[7];               // 1600000

    cudaFuncSetAttribute(gemm_mma_kernel,
                         cudaFuncAttributeMaxDynamicSharedMemorySize, GT_SMEM);

    void* pxh; cudaGetSymbolAddress(&pxh, g_xh);
    void* p0;  cudaGetSymbolAddress(&p0, g_h0);
    void* p1;  cudaGetSymbolAddress(&p1, g_h1);
    void* p2;  cudaGetSymbolAddress(&p2, g_h2);
    void* pw;  cudaGetSymbolAddress(&pw, g_wt);
    __half* xh = (__half*)pxh;
    __half* h0 = (__half*)p0;
    __half* h1 = (__half*)p1;
    __half* h2 = (__half*)p2;
    __half* wt = (__half*)pw;

    setup_kernel<<<(n + 255) / 256, 256>>>(Ws[0], Ws[1], Ws[2], n);
    count_deg_kernel<<<(e + 255) / 256, 256>>>(src, dst, e);
    norm_scan_kernel<<<1, 1024>>>(n);
    order_kernel<<<(n + 255) / 256, 256>>>(n);
    fill_csr_kernel<<<(e + 255) / 256, 256>>>(src, dst, e);
    prep_x_kernel<<<(int)(((size_t)n * 32 + 255) / 256), 256>>>(x, n);

    int gtiles = (n + 127) / 128;
    int gblocks = (int)(((size_t)n * 32 + 255) / 256);

    gather_kernel<<<gblocks, 256>>>(xh, n);
    gemm_mma_kernel<<<gtiles, 256, GT_SMEM>>>(wt, bs[0], h0, n, 1);
    gather_kernel<<<gblocks, 256>>>(h0, n);
    gemm_mma_kernel<<<gtiles, 256, GT_SMEM>>>(wt + DD * DD, bs[1], h1, n, 1);
    gather_kernel<<<gblocks, 256>>>(h1, n);
    gemm_mma_kernel<<<gtiles, 256, GT_SMEM>>>(wt + 2 * DD * DD, bs[2], h2, n, 0);

    pool_kernel<<<(n + 127) / 128, 256>>>(h2, gid, n);
    divide_kernel<<<(GG * DD + 255) / 256, 256>>>((float*)d_out);
}

// round 14
// speedup vs baseline: 1.1332x; 1.0226x over previous
#include <cuda_runtime.h>
#include <cuda_fp16.h>
#include <cuda_bf16.h>
#include <cstdint>

#define NN 100000
#define DD 128
#define GG 64

// Scratch (__device__ globals; no allocation allowed)
__device__ __align__(16) __half g_xh[NN * DD];     // x * cs, fp16
__device__ __align__(16) __half g_h0[NN * DD];     // layer outputs (fp16)
__device__ __align__(16) __half g_h1[NN * DD];
__device__ __align__(16) __half g_h2[NN * DD];
__device__ __align__(16) __half g_agg[NN * DD];    // gathered+cd-scaled rows (fp16)
__device__ __align__(16) __half g_wt[3 * DD * DD]; // W transposed + fp16: wt[l][n][k]
__device__ float g_cs[NN];
__device__ float g_cd[NN];
__device__ int   g_degout[NN];
__device__ int   g_degin[NN];
__device__ int   g_rowstart[NN];
__device__ int   g_cursor[NN];                     // seeded to rowstart; atomic bump = slot
__device__ int   g_csr[1700000];
__device__ __align__(16) float g_sums[GG * DD];
__device__ float g_cnt[GG];

// ---------------------------------------------------------------------------
__global__ void count_deg_kernel(const int* __restrict__ src,
                                 const int* __restrict__ dst, int e) {
    int i = blockIdx.x * blockDim.x + threadIdx.x;
    if (i < e) {
        atomicAdd(&g_degout[src[i]], 1);
        atomicAdd(&g_degin[dst[i]], 1);
    }
}

// Single-CTA scan over degin -> rowstart (+cursor=rowstart), plus norms.
__global__ void norm_scan_kernel(int n) {
    __shared__ int s[1024];
    int t = threadIdx.x;
    int chunk = (n + 1023) >> 10;
    int lo = min(t * chunk, n), hi = min(lo + chunk, n);
    int sum = 0;
    for (int i = lo; i < hi; i++) sum += g_degin[i];
    s[t] = sum;
    __syncthreads();
#pragma unroll
    for (int off = 1; off < 1024; off <<= 1) {
        int add = (t >= off) ? s[t - off] : 0;
        __syncthreads();
        s[t] += add;
        __syncthreads();
    }
    int run = s[t] - sum;   // exclusive
    for (int i = lo; i < hi; i++) {
        g_rowstart[i] = run;
        g_cursor[i] = run;           // cursor doubles as the write position
        run += g_degin[i];
    }
    for (int i = t; i < n; i += 1024) {
        g_cs[i] = rsqrtf((float)(g_degout[i] + 1));
        g_cd[i] = rsqrtf((float)(g_degin[i] + 1));
    }
}

// Fused: CSR fill (threads < e) + xh prep (threads < n*32). Both depend only
// on norm_scan outputs; merging saves a launch and keeps gather at launch #4.
__global__ void fill_prep_kernel(const int* __restrict__ src,
                                 const int* __restrict__ dst,
                                 const float* __restrict__ x, int e, int n) {
    int i = blockIdx.x * blockDim.x + threadIdx.x;
    if (i < e) {
        int pos = atomicAdd(&g_cursor[dst[i]], 1);
        g_csr[pos] = src[i];
    }
    if (i < n * 32) {
        int node = i >> 5, q = i & 31;
        float c = g_cs[node];
        float4 v = __ldg((const float4*)x + (size_t)node * 32 + q);
        uint2 o;
        *(__half2*)&o.x = __float22half2_rn(make_float2(v.x * c, v.y * c));
        *(__half2*)&o.y = __float22half2_rn(make_float2(v.z * c, v.w * c));
        ((uint2*)g_xh)[(size_t)node * 32 + q] = o;
    }
}

// W transpose + fp16 for all 3 layers
__global__ void prep_w_kernel(const float* __restrict__ W0, const float* __restrict__ W1,
                              const float* __restrict__ W2) {
    int i = blockIdx.x * blockDim.x + threadIdx.x;
    if (i < 3 * DD * DD) {
        const float* W = (i < DD * DD) ? W0 : ((i < 2 * DD * DD) ? W1 : W2);
        int j = i & (DD * DD - 1);
        int k = j >> 7, nn = j & 127;
        g_wt[(i >> 14) * DD * DD + nn * DD + k] = __float2half(W[j]);
    }
}

// ---------------------------------------------------------------------------
// Gather: agg[node] = half( cd[node] * ( hs[node] + sum_in hs[src] ) )
// One warp per node; each 256B row read as two single-line 128B LDGs
// (no within-LDG multi-line replays). Unroll 8 edges -> 16 loads in flight.
// ---------------------------------------------------------------------------
__global__ void __launch_bounds__(256)
gather_kernel(const __half* __restrict__ h, int n) {
    int w = (blockIdx.x * blockDim.x + threadIdx.x) >> 5;
    int lane = threadIdx.x & 31;
    if (w >= n) return;
    int node = w;
    int base = g_rowstart[node];
    int deg  = g_degin[node];

    const uint32_t* selfrow = (const uint32_t*)(h + (size_t)node * DD);
    uint32_t a0 = __ldg(selfrow + lane);
    uint32_t a1 = __ldg(selfrow + 32 + lane);
    float2 f0 = __half22float2(*(__half2*)&a0);
    float2 f1 = __half22float2(*(__half2*)&a1);
    float4 acc = make_float4(f0.x, f0.y, f1.x, f1.y);

    for (int j0 = 0; j0 < deg; j0 += 32) {
        int cnt = min(32, deg - j0);
        int sj = (lane < cnt) ? __ldg(&g_csr[base + j0 + lane]) : 0;
        int k = 0;
        for (; k + 8 <= cnt; k += 8) {
            int s[8];
#pragma unroll
            for (int u = 0; u < 8; u++) s[u] = __shfl_sync(0xffffffffu, sj, k + u);
            uint32_t v0[8], v1[8];
#pragma unroll
            for (int u = 0; u < 8; u++) {
                const uint32_t* rp = (const uint32_t*)(h + (size_t)s[u] * DD);
                v0[u] = __ldg(rp + lane);        // line 0 of the row
                v1[u] = __ldg(rp + 32 + lane);   // line 1 of the row
            }
#pragma unroll
            for (int u = 0; u < 8; u++) {
                float2 b0 = __half22float2(*(__half2*)&v0[u]);
                float2 b1 = __half22float2(*(__half2*)&v1[u]);
                acc.x += b0.x; acc.y += b0.y; acc.z += b1.x; acc.w += b1.y;
            }
        }
        for (; k < cnt; k++) {
            int s0 = __shfl_sync(0xffffffffu, sj, k);
            const uint32_t* rp = (const uint32_t*)(h + (size_t)s0 * DD);
            uint32_t u0 = __ldg(rp + lane);
            uint32_t u1 = __ldg(rp + 32 + lane);
            float2 b0 = __half22float2(*(__half2*)&u0);
            float2 b1 = __half22float2(*(__half2*)&u1);
            acc.x += b0.x; acc.y += b0.y; acc.z += b1.x; acc.w += b1.y;
        }
    }

    float cdv = g_cd[node];
    uint32_t o0, o1;
    *(__half2*)&o0 = __float22half2_rn(make_float2(acc.x * cdv, acc.y * cdv));
    *(__half2*)&o1 = __float22half2_rn(make_float2(acc.z * cdv, acc.w * cdv));
    uint32_t* orow = (uint32_t*)(g_agg + (size_t)node * DD);
    orow[lane] = o0;
    orow[32 + lane] = o1;
}

// ---------------------------------------------------------------------------
// Tensor-core GEMM, fp16 inputs / fp32 accum (mma.sync m16n8k16).
// out = half( relu(agg @ W + b) [* cs[row]] ). One CTA per 128 rows, 8 warps
// each 32(M)x64(N). Smem stride 136 halfs -> conflict-free fragment loads.
// ---------------------------------------------------------------------------
#define ASTR 136
#define GT_SMEM (2 * 128 * ASTR * 2)

__global__ void __launch_bounds__(256, 1)
gemm_mma_kernel(const __half* __restrict__ wt, const float* __restrict__ b,
                __half* __restrict__ out, int n, int cs_out) {
    extern __shared__ __half sh[];
    __half* Bsm = sh;               // 128 x ASTR : Wt[n][k]
    __half* Asm = sh + 128 * ASTR;  // 128 x ASTR : A[m][k]

    int t = threadIdx.x;
    int rows0 = blockIdx.x * 128;

#pragma unroll
    for (int it = 0; it < 8; it++) {
        int idx = t + it * 256;
        int r = idx >> 4, c = idx & 15;
        *(uint4*)&Bsm[r * ASTR + c * 8] = __ldg((const uint4*)wt + idx);
    }
#pragma unroll
    for (int it = 0; it < 8; it++) {
        int idx = t + it * 256;
        int r = idx >> 4, c = idx & 15;
        int gr = rows0 + r;
        if (gr > n - 1) gr = n - 1;
        *(uint4*)&Asm[r * ASTR + c * 8] = __ldg((const uint4*)(g_agg + (size_t)gr * DD) + c);
    }
    __syncthreads();

    int wid = t >> 5, lane = t & 31;
    int groupID = lane >> 2, ktid = lane & 3;
    int warpM = (wid & 3) * 32;
    int warpN = (wid >> 2) * 64;

    float acc[2][8][4];
#pragma unroll
    for (int mt = 0; mt < 2; mt++)
#pragma unroll
        for (int nt = 0; nt < 8; nt++)
#pragma unroll
            for (int q = 0; q < 4; q++) acc[mt][nt][q] = 0.0f;

#pragma unroll
    for (int k0 = 0; k0 < 128; k0 += 16) {
        uint32_t a[2][4];
#pragma unroll
        for (int mt = 0; mt < 2; mt++) {
            int r0 = warpM + mt * 16 + groupID;
            a[mt][0] = *(const uint32_t*)&Asm[r0 * ASTR + k0 + ktid * 2];
            a[mt][1] = *(const uint32_t*)&Asm[(r0 + 8) * ASTR + k0 + ktid * 2];
            a[mt][2] = *(const uint32_t*)&Asm[r0 * ASTR + k0 + ktid * 2 + 8];
            a[mt][3] = *(const uint32_t*)&Asm[(r0 + 8) * ASTR + k0 + ktid * 2 + 8];
        }
#pragma unroll
        for (int nt = 0; nt < 8; nt++) {
            int c0 = warpN + nt * 8 + groupID;
            uint32_t b0 = *(const uint32_t*)&Bsm[c0 * ASTR + k0 + ktid * 2];
            uint32_t b1 = *(const uint32_t*)&Bsm[c0 * ASTR + k0 + ktid * 2 + 8];
#pragma unroll
            for (int mt = 0; mt < 2; mt++) {
                asm volatile(
                    "mma.sync.aligned.m16n8k16.row.col.f32.f16.f16.f32 "
                    "{%0,%1,%2,%3}, {%4,%5,%6,%7}, {%8,%9}, {%0,%1,%2,%3};"
                    : "+f"(acc[mt][nt][0]), "+f"(acc[mt][nt][1]),
                      "+f"(acc[mt][nt][2]), "+f"(acc[mt][nt][3])
                    : "r"(a[mt][0]), "r"(a[mt][1]), "r"(a[mt][2]), "r"(a[mt][3]),
                      "r"(b0), "r"(b1));
            }
        }
    }

#pragma unroll
    for (int mt = 0; mt < 2; mt++) {
        int r0 = rows0 + warpM + mt * 16 + groupID;
        int r1 = r0 + 8;
        float sc0 = 1.0f, sc1 = 1.0f;
        if (cs_out) {
            if (r0 < n) sc0 = g_cs[r0];
            if (r1 < n) sc1 = g_cs[r1];
        }
#pragma unroll
        for (int nt = 0; nt < 8; nt++) {
            int col = warpN + nt * 8 + 2 * ktid;
            float2 bb = __ldg((const float2*)(b + col));
            if (r0 < n) {
                float2 o = make_float2(fmaxf(acc[mt][nt][0] + bb.x, 0.0f) * sc0,
                                       fmaxf(acc[mt][nt][1] + bb.y, 0.0f) * sc0);
                *(__half2*)(out + (size_t)r0 * DD + col) = __float22half2_rn(o);
            }
            if (r1 < n) {
                float2 o = make_float2(fmaxf(acc[mt][nt][2] + bb.x, 0.0f) * sc1,
                                       fmaxf(acc[mt][nt][3] + bb.y, 0.0f) * sc1);
                *(__half2*)(out + (size_t)r1 * DD + col) = __float22half2_rn(o);
            }
        }
    }
}

// ---------------------------------------------------------------------------
// Pooling: graph_ids sorted -> run-based accumulation, flush per run.
// ---------------------------------------------------------------------------
__global__ void pool_kernel(const __half* __restrict__ h,
                            const int* __restrict__ gid, int n) {
    int w = (blockIdx.x * blockDim.x + threadIdx.x) >> 5;
    int lane = threadIdx.x & 31;
    int n0 = w * 16;
    if (n0 >= n) return;
    int n1 = min(n0 + 16, n);

    float4 acc = make_float4(0.f, 0.f, 0.f, 0.f);
    int curg = gid[n0];
    int cnt = 0;
    for (int node = n0; node < n1; node++) {
        int g = gid[node];
        if (g != curg) {
            float* o = g_sums + curg * DD + lane * 4;
            asm volatile("red.global.add.v4.f32 [%0], {%1, %2, %3, %4};"
                         :: "l"(o), "f"(acc.x), "f"(acc.y), "f"(acc.z), "f"(acc.w)
                         : "memory");
            if (lane == 0) atomicAdd(&g_cnt[curg], (float)cnt);
            acc = make_float4(0.f, 0.f, 0.f, 0.f);
            curg = g; cnt = 0;
        }
        uint2 v = __ldg((const uint2*)h + (size_t)node * 32 + lane);
        float2 a0 = __half22float2(*(__half2*)&v.x);
        float2 a1 = __half22float2(*(__half2*)&v.y);
        acc.x += a0.x; acc.y += a0.y; acc.z += a1.x; acc.w += a1.y;
        cnt++;
    }
    float* o = g_sums + curg * DD + lane * 4;
    asm volatile("red.global.add.v4.f32 [%0], {%1, %2, %3, %4};"
                 :: "l"(o), "f"(acc.x), "f"(acc.y), "f"(acc.z), "f"(acc.w)
                 : "memory");
    if (lane == 0) atomicAdd(&g_cnt[curg], (float)cnt);
}

__global__ void divide_kernel(float* __restrict__ out) {
    int i = blockIdx.x * blockDim.x + threadIdx.x;
    if (i < GG * DD) out[i] = g_sums[i] / fmaxf(g_cnt[i >> 7], 1.0f);
}

// ---------------------------------------------------------------------------
extern "C" void kernel_launch(void* const* d_in, const int* in_sizes, int n_in,
                              void* d_out, int out_size) {
    const float* x  = (const float*)d_in[0];
    const float* Ws[3] = {(const float*)d_in[1], (const float*)d_in[3], (const float*)d_in[5]};
    const float* bs[3] = {(const float*)d_in[2], (const float*)d_in[4], (const float*)d_in[6]};
    const int* src = (const int*)d_in[7];
    const int* dst = (const int*)d_in[8];
    const int* gid = (const int*)d_in[9];

    int n = in_sizes[0] / DD;          // 100000
    int e = in_sizes[7];               // 1600000

    cudaFuncSetAttribute(gemm_mma_kernel,
                         cudaFuncAttributeMaxDynamicSharedMemorySize, GT_SMEM);

    void* pxh; cudaGetSymbolAddress(&pxh, g_xh);
    void* p0;  cudaGetSymbolAddress(&p0, g_h0);
    void* p1;  cudaGetSymbolAddress(&p1, g_h1);
    void* p2;  cudaGetSymbolAddress(&p2, g_h2);
    void* pw;  cudaGetSymbolAddress(&pw, g_wt);
    void* pdo; cudaGetSymbolAddress(&pdo, g_degout);
    void* pdi; cudaGetSymbolAddress(&pdi, g_degin);
    void* psu; cudaGetSymbolAddress(&psu, g_sums);
    void* pcn; cudaGetSymbolAddress(&pcn, g_cnt);
    __half* xh = (__half*)pxh;
    __half* h0 = (__half*)p0;
    __half* h1 = (__half*)p1;
    __half* h2 = (__half*)p2;
    __half* wt = (__half*)pw;

    // Zeroing via memset nodes (not kernel launches)
    cudaMemsetAsync(pdo, 0, (size_t)n * sizeof(int));
    cudaMemsetAsync(pdi, 0, (size_t)n * sizeof(int));
    cudaMemsetAsync(psu, 0, GG * DD * sizeof(float));
    cudaMemsetAsync(pcn, 0, GG * sizeof(float));

    int gtiles = (n + 127) / 128;
    int gblocks = (int)(((size_t)n * 32 + 255) / 256);

    count_deg_kernel<<<(e + 255) / 256, 256>>>(src, dst, e);                 // launch 1
    norm_scan_kernel<<<1, 1024>>>(n);                                        // launch 2
    fill_prep_kernel<<<(int)(((size_t)n * 32 + 255) / 256), 256>>>(src, dst, x, e, n); // launch 3
    gather_kernel<<<gblocks, 256>>>(xh, n);                                  // launch 4 (profiled)
    prep_w_kernel<<<192, 256>>>(Ws[0], Ws[1], Ws[2]);                        // launch 5
    gemm_mma_kernel<<<gtiles, 256, GT_SMEM>>>(wt, bs[0], h0, n, 1);
    gather_kernel<<<gblocks, 256>>>(h0, n);
    gemm_mma_kernel<<<gtiles, 256, GT_SMEM>>>(wt + DD * DD, bs[1], h1, n, 1);
    gather_kernel<<<gblocks, 256>>>(h1, n);
    gemm_mma_kernel<<<gtiles, 256, GT_SMEM>>>(wt + 2 * DD * DD, bs[2], h2, n, 0);

    pool_kernel<<<(n + 127) / 128, 256>>>(h2, gid, n);
    divide_kernel<<<(GG * DD + 255) / 256, 256>>>((float*)d_out);
}

// round 15
// speedup vs baseline: 1.1474x; 1.0125x over previous
#include <cuda_runtime.h>
#include <cuda_fp16.h>
#include <cuda_bf16.h>
#include <cstdint>

#define NN 100000
#define DD 128
#define GG 64

// Scratch (__device__ globals; no allocation allowed)
__device__ __align__(16) __half g_xh[NN * DD];     // x * cs, fp16
__device__ __align__(16) __half g_h0[NN * DD];     // layer outputs (fp16)
__device__ __align__(16) __half g_h1[NN * DD];
__device__ __align__(16) __half g_h2[NN * DD];
__device__ __align__(16) __half g_agg[NN * DD];    // gathered+cd-scaled rows (fp16)
__device__ __align__(16) __half g_wt[3 * DD * DD]; // W transposed + fp16: wt[l][n][k]
__device__ float g_cs[NN];
__device__ float g_cd[NN];
__device__ int   g_degout[NN];
__device__ int   g_degin[NN];
__device__ int   g_rowstart[NN];
__device__ int   g_cursor[NN];                     // seeded to rowstart; atomic bump = slot
__device__ int   g_csr[1700000];
__device__ __align__(16) float g_sums[GG * DD];
__device__ float g_cnt[GG];

// ---------------------------------------------------------------------------
__global__ void count_deg_kernel(const int* __restrict__ src,
                                 const int* __restrict__ dst, int e) {
    int i = blockIdx.x * blockDim.x + threadIdx.x;
    if (i < e) {
        atomicAdd(&g_degout[src[i]], 1);
        atomicAdd(&g_degin[dst[i]], 1);
    }
}

// Single-CTA scan over degin -> rowstart (+cursor=rowstart), plus norms.
__global__ void norm_scan_kernel(int n) {
    __shared__ int s[1024];
    int t = threadIdx.x;
    int chunk = (n + 1023) >> 10;
    int lo = min(t * chunk, n), hi = min(lo + chunk, n);
    int sum = 0;
    for (int i = lo; i < hi; i++) sum += g_degin[i];
    s[t] = sum;
    __syncthreads();
#pragma unroll
    for (int off = 1; off < 1024; off <<= 1) {
        int add = (t >= off) ? s[t - off] : 0;
        __syncthreads();
        s[t] += add;
        __syncthreads();
    }
    int run = s[t] - sum;   // exclusive
    for (int i = lo; i < hi; i++) {
        g_rowstart[i] = run;
        g_cursor[i] = run;           // cursor doubles as the write position
        run += g_degin[i];
    }
    for (int i = t; i < n; i += 1024) {
        g_cs[i] = rsqrtf((float)(g_degout[i] + 1));
        g_cd[i] = rsqrtf((float)(g_degin[i] + 1));
    }
}

// Fused: CSR fill (i < e) + xh prep (i < n*32) + W transpose/fp16 (i < 3*DD*DD)
__global__ void fill_prep_kernel(const int* __restrict__ src,
                                 const int* __restrict__ dst,
                                 const float* __restrict__ x,
                                 const float* __restrict__ W0,
                                 const float* __restrict__ W1,
                                 const float* __restrict__ W2, int e, int n) {
    int i = blockIdx.x * blockDim.x + threadIdx.x;
    if (i < e) {
        int pos = atomicAdd(&g_cursor[dst[i]], 1);
        g_csr[pos] = src[i];
    }
    if (i < n * 32) {
        int node = i >> 5, q = i & 31;
        float c = g_cs[node];
        float4 v = __ldg((const float4*)x + (size_t)node * 32 + q);
        uint2 o;
        *(__half2*)&o.x = __float22half2_rn(make_float2(v.x * c, v.y * c));
        *(__half2*)&o.y = __float22half2_rn(make_float2(v.z * c, v.w * c));
        ((uint2*)g_xh)[(size_t)node * 32 + q] = o;
    }
    if (i < 3 * DD * DD) {
        const float* W = (i < DD * DD) ? W0 : ((i < 2 * DD * DD) ? W1 : W2);
        int j = i & (DD * DD - 1);
        int k = j >> 7, nn = j & 127;
        g_wt[(i >> 14) * DD * DD + nn * DD + k] = __float2half(W[j]);
    }
}

// ---------------------------------------------------------------------------
// Gather: agg[node] = half( cd[node] * ( hs[node] + sum_in hs[src] ) )
// ISSUE-BOUND (ncu: issue 58.8%, fma 35.7%, L2 only 37%): cut instructions per
// edge with an fp16 tree pre-reduction. Groups of 4 edges are summed with
// __hadd2 (1 instr vs cvt+cvt+add+add), then converted/accumulated into the
// fp32 master accumulator. ~54 instr per 8 edges vs ~104 before.
// Rows read as two single-line 128B LDGs per edge (no multi-line replays).
// ---------------------------------------------------------------------------
__global__ void __launch_bounds__(256)
gather_kernel(const __half* __restrict__ h, int n) {
    int w = (blockIdx.x * blockDim.x + threadIdx.x) >> 5;
    int lane = threadIdx.x & 31;
    if (w >= n) return;
    int node = w;
    int base = g_rowstart[node];
    int deg  = g_degin[node];

    const __half2* selfrow = (const __half2*)(h + (size_t)node * DD);
    float2 f0 = __half22float2(__ldg(selfrow + lane));
    float2 f1 = __half22float2(__ldg(selfrow + 32 + lane));
    float4 acc = make_float4(f0.x, f0.y, f1.x, f1.y);

    for (int j0 = 0; j0 < deg; j0 += 32) {
        int cnt = min(32, deg - j0);
        int sj = (lane < cnt) ? __ldg(&g_csr[base + j0 + lane]) : 0;
        int k = 0;
        for (; k + 8 <= cnt; k += 8) {
            int s[8];
#pragma unroll
            for (int u = 0; u < 8; u++) s[u] = __shfl_sync(0xffffffffu, sj, k + u);
            __half2 v0[8], v1[8];
#pragma unroll
            for (int u = 0; u < 8; u++) {
                const __half2* rp = (const __half2*)(h + (size_t)s[u] * DD);
                v0[u] = __ldg(rp + lane);        // line 0 of the row
                v1[u] = __ldg(rp + 32 + lane);   // line 1 of the row
            }
            // fp16 tree reduction over groups of 4 edges, then fp32 accumulate
            __half2 p0 = __hadd2(__hadd2(v0[0], v0[1]), __hadd2(v0[2], v0[3]));
            __half2 p1 = __hadd2(__hadd2(v0[4], v0[5]), __hadd2(v0[6], v0[7]));
            __half2 q0 = __hadd2(__hadd2(v1[0], v1[1]), __hadd2(v1[2], v1[3]));
            __half2 q1 = __hadd2(__hadd2(v1[4], v1[5]), __hadd2(v1[6], v1[7]));
            float2 f;
            f = __half22float2(p0); acc.x += f.x; acc.y += f.y;
            f = __half22float2(p1); acc.x += f.x; acc.y += f.y;
            f = __half22float2(q0); acc.z += f.x; acc.w += f.y;
            f = __half22float2(q1); acc.z += f.x; acc.w += f.y;
        }
        for (; k < cnt; k++) {
            int s0 = __shfl_sync(0xffffffffu, sj, k);
            const __half2* rp = (const __half2*)(h + (size_t)s0 * DD);
            float2 b0 = __half22float2(__ldg(rp + lane));
            float2 b1 = __half22float2(__ldg(rp + 32 + lane));
            acc.x += b0.x; acc.y += b0.y; acc.z += b1.x; acc.w += b1.y;
        }
    }

    float cdv = g_cd[node];
    uint32_t o0, o1;
    *(__half2*)&o0 = __float22half2_rn(make_float2(acc.x * cdv, acc.y * cdv));
    *(__half2*)&o1 = __float22half2_rn(make_float2(acc.z * cdv, acc.w * cdv));
    uint32_t* orow = (uint32_t*)(g_agg + (size_t)node * DD);
    orow[lane] = o0;
    orow[32 + lane] = o1;
}

// ---------------------------------------------------------------------------
// Tensor-core GEMM, fp16 inputs / fp32 accum (mma.sync m16n8k16).
// out = half( relu(agg @ W + b) [* cs[row]] ). One CTA per 128 rows, 8 warps
// each 32(M)x64(N). Smem stride 136 halfs -> conflict-free fragment loads.
// ---------------------------------------------------------------------------
#define ASTR 136
#define GT_SMEM (2 * 128 * ASTR * 2)

__global__ void __launch_bounds__(256, 1)
gemm_mma_kernel(const __half* __restrict__ wt, const float* __restrict__ b,
                __half* __restrict__ out, int n, int cs_out) {
    extern __shared__ __half sh[];
    __half* Bsm = sh;               // 128 x ASTR : Wt[n][k]
    __half* Asm = sh + 128 * ASTR;  // 128 x ASTR : A[m][k]

    int t = threadIdx.x;
    int rows0 = blockIdx.x * 128;

#pragma unroll
    for (int it = 0; it < 8; it++) {
        int idx = t + it * 256;
        int r = idx >> 4, c = idx & 15;
        *(uint4*)&Bsm[r * ASTR + c * 8] = __ldg((const uint4*)wt + idx);
    }
#pragma unroll
    for (int it = 0; it < 8; it++) {
        int idx = t + it * 256;
        int r = idx >> 4, c = idx & 15;
        int gr = rows0 + r;
        if (gr > n - 1) gr = n - 1;
        *(uint4*)&Asm[r * ASTR + c * 8] = __ldg((const uint4*)(g_agg + (size_t)gr * DD) + c);
    }
    __syncthreads();

    int wid = t >> 5, lane = t & 31;
    int groupID = lane >> 2, ktid = lane & 3;
    int warpM = (wid & 3) * 32;
    int warpN = (wid >> 2) * 64;

    float acc[2][8][4];
#pragma unroll
    for (int mt = 0; mt < 2; mt++)
#pragma unroll
        for (int nt = 0; nt < 8; nt++)
#pragma unroll
            for (int q = 0; q < 4; q++) acc[mt][nt][q] = 0.0f;

#pragma unroll
    for (int k0 = 0; k0 < 128; k0 += 16) {
        uint32_t a[2][4];
#pragma unroll
        for (int mt = 0; mt < 2; mt++) {
            int r0 = warpM + mt * 16 + groupID;
            a[mt][0] = *(const uint32_t*)&Asm[r0 * ASTR + k0 + ktid * 2];
            a[mt][1] = *(const uint32_t*)&Asm[(r0 + 8) * ASTR + k0 + ktid * 2];
            a[mt][2] = *(const uint32_t*)&Asm[r0 * ASTR + k0 + ktid * 2 + 8];
            a[mt][3] = *(const uint32_t*)&Asm[(r0 + 8) * ASTR + k0 + ktid * 2 + 8];
        }
#pragma unroll
        for (int nt = 0; nt < 8; nt++) {
            int c0 = warpN + nt * 8 + groupID;
            uint32_t b0 = *(const uint32_t*)&Bsm[c0 * ASTR + k0 + ktid * 2];
            uint32_t b1 = *(const uint32_t*)&Bsm[c0 * ASTR + k0 + ktid * 2 + 8];
#pragma unroll
            for (int mt = 0; mt < 2; mt++) {
                asm volatile(
                    "mma.sync.aligned.m16n8k16.row.col.f32.f16.f16.f32 "
                    "{%0,%1,%2,%3}, {%4,%5,%6,%7}, {%8,%9}, {%0,%1,%2,%3};"
                    : "+f"(acc[mt][nt][0]), "+f"(acc[mt][nt][1]),
                      "+f"(acc[mt][nt][2]), "+f"(acc[mt][nt][3])
                    : "r"(a[mt][0]), "r"(a[mt][1]), "r"(a[mt][2]), "r"(a[mt][3]),
                      "r"(b0), "r"(b1));
            }
        }
    }

#pragma unroll
    for (int mt = 0; mt < 2; mt++) {
        int r0 = rows0 + warpM + mt * 16 + groupID;
        int r1 = r0 + 8;
        float sc0 = 1.0f, sc1 = 1.0f;
        if (cs_out) {
            if (r0 < n) sc0 = g_cs[r0];
            if (r1 < n) sc1 = g_cs[r1];
        }
#pragma unroll
        for (int nt = 0; nt < 8; nt++) {
            int col = warpN + nt * 8 + 2 * ktid;
            float2 bb = __ldg((const float2*)(b + col));
            if (r0 < n) {
                float2 o = make_float2(fmaxf(acc[mt][nt][0] + bb.x, 0.0f) * sc0,
                                       fmaxf(acc[mt][nt][1] + bb.y, 0.0f) * sc0);
                *(__half2*)(out + (size_t)r0 * DD + col) = __float22half2_rn(o);
            }
            if (r1 < n) {
                float2 o = make_float2(fmaxf(acc[mt][nt][2] + bb.x, 0.0f) * sc1,
                                       fmaxf(acc[mt][nt][3] + bb.y, 0.0f) * sc1);
                *(__half2*)(out + (size_t)r1 * DD + col) = __float22half2_rn(o);
            }
        }
    }
}

// ---------------------------------------------------------------------------
// Pooling: graph_ids sorted -> run-based accumulation, flush per run.
// ---------------------------------------------------------------------------
__global__ void pool_kernel(const __half* __restrict__ h,
                            const int* __restrict__ gid, int n) {
    int w = (blockIdx.x * blockDim.x + threadIdx.x) >> 5;
    int lane = threadIdx.x & 31;
    int n0 = w * 16;
    if (n0 >= n) return;
    int n1 = min(n0 + 16, n);

    float4 acc = make_float4(0.f, 0.f, 0.f, 0.f);
    int curg = gid[n0];
    int cnt = 0;
    for (int node = n0; node < n1; node++) {
        int g = gid[node];
        if (g != curg) {
            float* o = g_sums + curg * DD + lane * 4;
            asm volatile("red.global.add.v4.f32 [%0], {%1, %2, %3, %4};"
                         :: "l"(o), "f"(acc.x), "f"(acc.y), "f"(acc.z), "f"(acc.w)
                         : "memory");
            if (lane == 0) atomicAdd(&g_cnt[curg], (float)cnt);
            acc = make_float4(0.f, 0.f, 0.f, 0.f);
            curg = g; cnt = 0;
        }
        uint2 v = __ldg((const uint2*)h + (size_t)node * 32 + lane);
        float2 a0 = __half22float2(*(__half2*)&v.x);
        float2 a1 = __half22float2(*(__half2*)&v.y);
        acc.x += a0.x; acc.y += a0.y; acc.z += a1.x; acc.w += a1.y;
        cnt++;
    }
    float* o = g_sums + curg * DD + lane * 4;
    asm volatile("red.global.add.v4.f32 [%0], {%1, %2, %3, %4};"
                 :: "l"(o), "f"(acc.x), "f"(acc.y), "f"(acc.z), "f"(acc.w)
                 : "memory");
    if (lane == 0) atomicAdd(&g_cnt[curg], (float)cnt);
}

__global__ void divide_kernel(float* __restrict__ out) {
    int i = blockIdx.x * blockDim.x + threadIdx.x;
    if (i < GG * DD) out[i] = g_sums[i] / fmaxf(g_cnt[i >> 7], 1.0f);
}

// ---------------------------------------------------------------------------
extern "C" void kernel_launch(void* const* d_in, const int* in_sizes, int n_in,
                              void* d_out, int out_size) {
    const float* x  = (const float*)d_in[0];
    const float* Ws[3] = {(const float*)d_in[1], (const float*)d_in[3], (const float*)d_in[5]};
    const float* bs[3] = {(const float*)d_in[2], (const float*)d_in[4], (const float*)d_in[6]};
    const int* src = (const int*)d_in[7];
    const int* dst = (const int*)d_in[8];
    const int* gid = (const int*)d_in[9];

    int n = in_sizes[0] / DD;          // 100000
    int e = in_sizes[7];               // 1600000

    cudaFuncSetAttribute(gemm_mma_kernel,
                         cudaFuncAttributeMaxDynamicSharedMemorySize, GT_SMEM);

    void* pxh; cudaGetSymbolAddress(&pxh, g_xh);
    void* p0;  cudaGetSymbolAddress(&p0, g_h0);
    void* p1;  cudaGetSymbolAddress(&p1, g_h1);
    void* p2;  cudaGetSymbolAddress(&p2, g_h2);
    void* pw;  cudaGetSymbolAddress(&pw, g_wt);
    void* pdo; cudaGetSymbolAddress(&pdo, g_degout);
    void* pdi; cudaGetSymbolAddress(&pdi, g_degin);
    void* psu; cudaGetSymbolAddress(&psu, g_sums);
    void* pcn; cudaGetSymbolAddress(&pcn, g_cnt);
    __half* xh = (__half*)pxh;
    __half* h0 = (__half*)p0;
    __half* h1 = (__half*)p1;
    __half* h2 = (__half*)p2;
    __half* wt = (__half*)pw;

    // Zeroing via memset nodes (not kernel launches)
    cudaMemsetAsync(pdo, 0, (size_t)n * sizeof(int));
    cudaMemsetAsync(pdi, 0, (size_t)n * sizeof(int));
    cudaMemsetAsync(psu, 0, GG * DD * sizeof(float));
    cudaMemsetAsync(pcn, 0, GG * sizeof(float));

    int gtiles = (n + 127) / 128;
    int gblocks = (int)(((size_t)n * 32 + 255) / 256);

    count_deg_kernel<<<(e + 255) / 256, 256>>>(src, dst, e);                 // launch 1
    norm_scan_kernel<<<1, 1024>>>(n);                                        // launch 2
    fill_prep_kernel<<<(int)(((size_t)n * 32 + 255) / 256), 256>>>(
        src, dst, x, Ws[0], Ws[1], Ws[2], e, n);                             // launch 3
    gather_kernel<<<gblocks, 256>>>(xh, n);                                  // launch 4 (profiled)
    gemm_mma_kernel<<<gtiles, 256, GT_SMEM>>>(wt, bs[0], h0, n, 1);
    gather_kernel<<<gblocks, 256>>>(h0, n);
    gemm_mma_kernel<<<gtiles, 256, GT_SMEM>>>(wt + DD * DD, bs[1], h1, n, 1);
    gather_kernel<<<gblocks, 256>>>(h1, n);
    gemm_mma_kernel<<<gtiles, 256, GT_SMEM>>>(wt + 2 * DD * DD, bs[2], h2, n, 0);

    pool_kernel<<<(n + 127) / 128, 256>>>(h2, gid, n);
    divide_kernel<<<(GG * DD + 255) / 256, 256>>>((float*)d_out);
}

// round 16
// speedup vs baseline: 1.2722x; 1.1088x over previous
#include <cuda_runtime.h>
#include <cuda_fp16.h>
#include <cuda_bf16.h>
#include <cstdint>

#define NN 100000
#define DD 128
#define GG 64

// Scratch (__device__ globals; no allocation allowed)
__device__ __align__(16) __half g_xh[NN * DD];     // x * cs, fp16
__device__ __align__(16) __half g_h0[NN * DD];     // layer outputs (fp16)
__device__ __align__(16) __half g_h1[NN * DD];
__device__ __align__(16) __half g_h2[NN * DD];
__device__ __align__(16) __half g_agg[NN * DD];    // gathered+cd-scaled rows (fp16)
__device__ __align__(16) __half g_wt[3 * DD * DD]; // W transposed + fp16: wt[l][n][k]
__device__ int   g_degout[NN];
__device__ int   g_degin[NN];
__device__ int   g_rowstart[NN];
__device__ int   g_cursor[NN];                     // seeded to rowstart; atomic bump = slot
__device__ int   g_csr[1700000];
__device__ __align__(16) float g_sums[GG * DD];
__device__ float g_cnt[GG];

// ---------------------------------------------------------------------------
__global__ void count_deg_kernel(const int* __restrict__ src,
                                 const int* __restrict__ dst, int e) {
    int i = blockIdx.x * blockDim.x + threadIdx.x;
    if (i < e) {
        atomicAdd(&g_degout[src[i]], 1);
        atomicAdd(&g_degin[dst[i]], 1);
    }
}

// Single-CTA int-only scan over degin -> rowstart (+cursor=rowstart).
// Norms (rsqrt) are computed inline at each use site, NOT here — 200k MUFU
// on a single SM was costing ~50-70us.
__global__ void scan_kernel(int n) {
    __shared__ int s[1024];
    int t = threadIdx.x;
    int chunk = (n + 1023) >> 10;
    int lo = min(t * chunk, n), hi = min(lo + chunk, n);
    int sum = 0;
    for (int i = lo; i < hi; i++) sum += g_degin[i];
    s[t] = sum;
    __syncthreads();
#pragma unroll
    for (int off = 1; off < 1024; off <<= 1) {
        int add = (t >= off) ? s[t - off] : 0;
        __syncthreads();
        s[t] += add;
        __syncthreads();
    }
    int run = s[t] - sum;   // exclusive
    for (int i = lo; i < hi; i++) {
        g_rowstart[i] = run;
        g_cursor[i] = run;           // cursor doubles as the write position
        run += g_degin[i];
    }
}

// Fused: CSR fill (i < e) + xh prep with inline cs (i < n*32) + W fp16 prep
__global__ void fill_prep_kernel(const int* __restrict__ src,
                                 const int* __restrict__ dst,
                                 const float* __restrict__ x,
                                 const float* __restrict__ W0,
                                 const float* __restrict__ W1,
                                 const float* __restrict__ W2, int e, int n) {
    int i = blockIdx.x * blockDim.x + threadIdx.x;
    if (i < e) {
        int pos = atomicAdd(&g_cursor[dst[i]], 1);
        g_csr[pos] = src[i];
    }
    if (i < n * 32) {
        int node = i >> 5, q = i & 31;
        float c = rsqrtf((float)(__ldg(&g_degout[node]) + 1));   // cs inline
        float4 v = __ldg((const float4*)x + (size_t)node * 32 + q);
        uint2 o;
        *(__half2*)&o.x = __float22half2_rn(make_float2(v.x * c, v.y * c));
        *(__half2*)&o.y = __float22half2_rn(make_float2(v.z * c, v.w * c));
        ((uint2*)g_xh)[(size_t)node * 32 + q] = o;
    }
    if (i < 3 * DD * DD) {
        const float* W = (i < DD * DD) ? W0 : ((i < 2 * DD * DD) ? W1 : W2);
        int j = i & (DD * DD - 1);
        int k = j >> 7, nn = j & 127;
        g_wt[(i >> 14) * DD * DD + nn * DD + k] = __float2half(W[j]);
    }
}

// ---------------------------------------------------------------------------
// Gather: agg[node] = half( cd[node] * ( hs[node] + sum_in hs[src] ) )
// cd computed inline from deg (already in a register). fp16 tree pre-reduce
// over 4-edge groups (__hadd2), fp32 master accumulator. Rows read as two
// single-line 128B LDGs (no multi-line replays).
// ---------------------------------------------------------------------------
__global__ void __launch_bounds__(256)
gather_kernel(const __half* __restrict__ h, int n) {
    int w = (blockIdx.x * blockDim.x + threadIdx.x) >> 5;
    int lane = threadIdx.x & 31;
    if (w >= n) return;
    int node = w;
    int base = g_rowstart[node];
    int deg  = g_degin[node];

    const __half2* selfrow = (const __half2*)(h + (size_t)node * DD);
    float2 f0 = __half22float2(__ldg(selfrow + lane));
    float2 f1 = __half22float2(__ldg(selfrow + 32 + lane));
    float4 acc = make_float4(f0.x, f0.y, f1.x, f1.y);

    for (int j0 = 0; j0 < deg; j0 += 32) {
        int cnt = min(32, deg - j0);
        int sj = (lane < cnt) ? __ldg(&g_csr[base + j0 + lane]) : 0;
        int k = 0;
        for (; k + 8 <= cnt; k += 8) {
            int s[8];
#pragma unroll
            for (int u = 0; u < 8; u++) s[u] = __shfl_sync(0xffffffffu, sj, k + u);
            __half2 v0[8], v1[8];
#pragma unroll
            for (int u = 0; u < 8; u++) {
                const __half2* rp = (const __half2*)(h + (size_t)s[u] * DD);
                v0[u] = __ldg(rp + lane);        // line 0 of the row
                v1[u] = __ldg(rp + 32 + lane);   // line 1 of the row
            }
            __half2 p0 = __hadd2(__hadd2(v0[0], v0[1]), __hadd2(v0[2], v0[3]));
            __half2 p1 = __hadd2(__hadd2(v0[4], v0[5]), __hadd2(v0[6], v0[7]));
            __half2 q0 = __hadd2(__hadd2(v1[0], v1[1]), __hadd2(v1[2], v1[3]));
            __half2 q1 = __hadd2(__hadd2(v1[4], v1[5]), __hadd2(v1[6], v1[7]));
            float2 f;
            f = __half22float2(p0); acc.x += f.x; acc.y += f.y;
            f = __half22float2(p1); acc.x += f.x; acc.y += f.y;
            f = __half22float2(q0); acc.z += f.x; acc.w += f.y;
            f = __half22float2(q1); acc.z += f.x; acc.w += f.y;
        }
        for (; k < cnt; k++) {
            int s0 = __shfl_sync(0xffffffffu, sj, k);
            const __half2* rp = (const __half2*)(h + (size_t)s0 * DD);
            float2 b0 = __half22float2(__ldg(rp + lane));
            float2 b1 = __half22float2(__ldg(rp + 32 + lane));
            acc.x += b0.x; acc.y += b0.y; acc.z += b1.x; acc.w += b1.y;
        }
    }

    float cdv = rsqrtf((float)(deg + 1));   // cd inline (deg already loaded)
    uint32_t o0, o1;
    *(__half2*)&o0 = __float22half2_rn(make_float2(acc.x * cdv, acc.y * cdv));
    *(__half2*)&o1 = __float22half2_rn(make_float2(acc.z * cdv, acc.w * cdv));
    uint32_t* orow = (uint32_t*)(g_agg + (size_t)node * DD);
    orow[lane] = o0;
    orow[32 + lane] = o1;
}

// ---------------------------------------------------------------------------
// Tensor-core GEMM, fp16 inputs / fp32 accum (mma.sync m16n8k16).
// out = half( relu(agg @ W + b) [* cs[row]] ), cs computed inline from degout.
// One CTA per 128 rows, 8 warps each 32(M)x64(N). Smem stride 136 halfs.
// ---------------------------------------------------------------------------
#define ASTR 136
#define GT_SMEM (2 * 128 * ASTR * 2)

__global__ void __launch_bounds__(256, 1)
gemm_mma_kernel(const __half* __restrict__ wt, const float* __restrict__ b,
                __half* __restrict__ out, int n, int cs_out) {
    extern __shared__ __half sh[];
    __half* Bsm = sh;               // 128 x ASTR : Wt[n][k]
    __half* Asm = sh + 128 * ASTR;  // 128 x ASTR : A[m][k]

    int t = threadIdx.x;
    int rows0 = blockIdx.x * 128;

#pragma unroll
    for (int it = 0; it < 8; it++) {
        int idx = t + it * 256;
        int r = idx >> 4, c = idx & 15;
        *(uint4*)&Bsm[r * ASTR + c * 8] = __ldg((const uint4*)wt + idx);
    }
#pragma unroll
    for (int it = 0; it < 8; it++) {
        int idx = t + it * 256;
        int r = idx >> 4, c = idx & 15;
        int gr = rows0 + r;
        if (gr > n - 1) gr = n - 1;
        *(uint4*)&Asm[r * ASTR + c * 8] = __ldg((const uint4*)(g_agg + (size_t)gr * DD) + c);
    }
    __syncthreads();

    int wid = t >> 5, lane = t & 31;
    int groupID = lane >> 2, ktid = lane & 3;
    int warpM = (wid & 3) * 32;
    int warpN = (wid >> 2) * 64;

    float acc[2][8][4];
#pragma unroll
    for (int mt = 0; mt < 2; mt++)
#pragma unroll
        for (int nt = 0; nt < 8; nt++)
#pragma unroll
            for (int q = 0; q < 4; q++) acc[mt][nt][q] = 0.0f;

#pragma unroll
    for (int k0 = 0; k0 < 128; k0 += 16) {
        uint32_t a[2][4];
#pragma unroll
        for (int mt = 0; mt < 2; mt++) {
            int r0 = warpM + mt * 16 + groupID;
            a[mt][0] = *(const uint32_t*)&Asm[r0 * ASTR + k0 + ktid * 2];
            a[mt][1] = *(const uint32_t*)&Asm[(r0 + 8) * ASTR + k0 + ktid * 2];
            a[mt][2] = *(const uint32_t*)&Asm[r0 * ASTR + k0 + ktid * 2 + 8];
            a[mt][3] = *(const uint32_t*)&Asm[(r0 + 8) * ASTR + k0 + ktid * 2 + 8];
        }
#pragma unroll
        for (int nt = 0; nt < 8; nt++) {
            int c0 = warpN + nt * 8 + groupID;
            uint32_t b0 = *(const uint32_t*)&Bsm[c0 * ASTR + k0 + ktid * 2];
            uint32_t b1 = *(const uint32_t*)&Bsm[c0 * ASTR + k0 + ktid * 2 + 8];
#pragma unroll
            for (int mt = 0; mt < 2; mt++) {
                asm volatile(
                    "mma.sync.aligned.m16n8k16.row.col.f32.f16.f16.f32 "
                    "{%0,%1,%2,%3}, {%4,%5,%6,%7}, {%8,%9}, {%0,%1,%2,%3};"
                    : "+f"(acc[mt][nt][0]), "+f"(acc[mt][nt][1]),
                      "+f"(acc[mt][nt][2]), "+f"(acc[mt][nt][3])
                    : "r"(a[mt][0]), "r"(a[mt][1]), "r"(a[mt][2]), "r"(a[mt][3]),
                      "r"(b0), "r"(b1));
            }
        }
    }

#pragma unroll
    for (int mt = 0; mt < 2; mt++) {
        int r0 = rows0 + warpM + mt * 16 + groupID;
        int r1 = r0 + 8;
        float sc0 = 1.0f, sc1 = 1.0f;
        if (cs_out) {
            if (r0 < n) sc0 = rsqrtf((float)(__ldg(&g_degout[r0]) + 1));
            if (r1 < n) sc1 = rsqrtf((float)(__ldg(&g_degout[r1]) + 1));
        }
#pragma unroll
        for (int nt = 0; nt < 8; nt++) {
            int col = warpN + nt * 8 + 2 * ktid;
            float2 bb = __ldg((const float2*)(b + col));
            if (r0 < n) {
                float2 o = make_float2(fmaxf(acc[mt][nt][0] + bb.x, 0.0f) * sc0,
                                       fmaxf(acc[mt][nt][1] + bb.y, 0.0f) * sc0);
                *(__half2*)(out + (size_t)r0 * DD + col) = __float22half2_rn(o);
            }
            if (r1 < n) {
                float2 o = make_float2(fmaxf(acc[mt][nt][2] + bb.x, 0.0f) * sc1,
                                       fmaxf(acc[mt][nt][3] + bb.y, 0.0f) * sc1);
                *(__half2*)(out + (size_t)r1 * DD + col) = __float22half2_rn(o);
            }
        }
    }
}

// ---------------------------------------------------------------------------
// Pooling: graph_ids sorted -> run-based accumulation, flush per run.
// ---------------------------------------------------------------------------
__global__ void pool_kernel(const __half* __restrict__ h,
                            const int* __restrict__ gid, int n) {
    int w = (blockIdx.x * blockDim.x + threadIdx.x) >> 5;
    int lane = threadIdx.x & 31;
    int n0 = w * 16;
    if (n0 >= n) return;
    int n1 = min(n0 + 16, n);

    float4 acc = make_float4(0.f, 0.f, 0.f, 0.f);
    int curg = gid[n0];
    int cnt = 0;
    for (int node = n0; node < n1; node++) {
        int g = gid[node];
        if (g != curg) {
            float* o = g_sums + curg * DD + lane * 4;
            asm volatile("red.global.add.v4.f32 [%0], {%1, %2, %3, %4};"
                         :: "l"(o), "f"(acc.x), "f"(acc.y), "f"(acc.z), "f"(acc.w)
                         : "memory");
            if (lane == 0) atomicAdd(&g_cnt[curg], (float)cnt);
            acc = make_float4(0.f, 0.f, 0.f, 0.f);
            curg = g; cnt = 0;
        }
        uint2 v = __ldg((const uint2*)h + (size_t)node * 32 + lane);
        float2 a0 = __half22float2(*(__half2*)&v.x);
        float2 a1 = __half22float2(*(__half2*)&v.y);
        acc.x += a0.x; acc.y += a0.y; acc.z += a1.x; acc.w += a1.y;
        cnt++;
    }
    float* o = g_sums + curg * DD + lane * 4;
    asm volatile("red.global.add.v4.f32 [%0], {%1, %2, %3, %4};"
                 :: "l"(o), "f"(acc.x), "f"(acc.y), "f"(acc.z), "f"(acc.w)
                 : "memory");
    if (lane == 0) atomicAdd(&g_cnt[curg], (float)cnt);
}

__global__ void divide_kernel(float* __restrict__ out) {
    int i = blockIdx.x * blockDim.x + threadIdx.x;
    if (i < GG * DD) out[i] = g_sums[i] / fmaxf(g_cnt[i >> 7], 1.0f);
}

// ---------------------------------------------------------------------------
extern "C" void kernel_launch(void* const* d_in, const int* in_sizes, int n_in,
                              void* d_out, int out_size) {
    const float* x  = (const float*)d_in[0];
    const float* Ws[3] = {(const float*)d_in[1], (const float*)d_in[3], (const float*)d_in[5]};
    const float* bs[3] = {(const float*)d_in[2], (const float*)d_in[4], (const float*)d_in[6]};
    const int* src = (const int*)d_in[7];
    const int* dst = (const int*)d_in[8];
    const int* gid = (const int*)d_in[9];

    int n = in_sizes[0] / DD;          // 100000
    int e = in_sizes[7];               // 1600000

    cudaFuncSetAttribute(gemm_mma_kernel,
                         cudaFuncAttributeMaxDynamicSharedMemorySize, GT_SMEM);

    void* pxh; cudaGetSymbolAddress(&pxh, g_xh);
    void* p0;  cudaGetSymbolAddress(&p0, g_h0);
    void* p1;  cudaGetSymbolAddress(&p1, g_h1);
    void* p2;  cudaGetSymbolAddress(&p2, g_h2);
    void* pw;  cudaGetSymbolAddress(&pw, g_wt);
    void* pdo; cudaGetSymbolAddress(&pdo, g_degout);
    void* pdi; cudaGetSymbolAddress(&pdi, g_degin);
    void* psu; cudaGetSymbolAddress(&psu, g_sums);
    void* pcn; cudaGetSymbolAddress(&pcn, g_cnt);
    __half* xh = (__half*)pxh;
    __half* h0 = (__half*)p0;
    __half* h1 = (__half*)p1;
    __half* h2 = (__half*)p2;
    __half* wt = (__half*)pw;

    // Zeroing via memset nodes (not kernel launches)
    cudaMemsetAsync(pdo, 0, (size_t)n * sizeof(int));
    cudaMemsetAsync(pdi, 0, (size_t)n * sizeof(int));
    cudaMemsetAsync(psu, 0, GG * DD * sizeof(float));
    cudaMemsetAsync(pcn, 0, GG * sizeof(float));

    int gtiles = (n + 127) / 128;
    int gblocks = (int)(((size_t)n * 32 + 255) / 256);

    count_deg_kernel<<<(e + 255) / 256, 256>>>(src, dst, e);                 // launch 1
    scan_kernel<<<1, 1024>>>(n);                                             // launch 2
    fill_prep_kernel<<<(int)(((size_t)n * 32 + 255) / 256), 256>>>(
        src, dst, x, Ws[0], Ws[1], Ws[2], e, n);                             // launch 3
    gather_kernel<<<gblocks, 256>>>(xh, n);                                  // launch 4 (profiled)
    gemm_mma_kernel<<<gtiles, 256, GT_SMEM>>>(wt, bs[0], h0, n, 1);
    gather_kernel<<<gblocks, 256>>>(h0, n);
    gemm_mma_kernel<<<gtiles, 256, GT_SMEM>>>(wt + DD * DD, bs[1], h1, n, 1);
    gather_kernel<<<gblocks, 256>>>(h1, n);
    gemm_mma_kernel<<<gtiles, 256, GT_SMEM>>>(wt + 2 * DD * DD, bs[2], h2, n, 0);

    pool_kernel<<<(n + 127) / 128, 256>>>(h2, gid, n);
    divide_kernel<<<(GG * DD + 255) / 256, 256>>>((float*)d_out);
}

// round 17
// speedup vs baseline: 1.3086x; 1.0286x over previous
#include <cuda_runtime.h>
#include <cuda_fp16.h>
#include <cuda_bf16.h>
#include <cstdint>

#define NN 100000
#define DD 128
#define GG 64

// Scratch (__device__ globals; no allocation allowed)
__device__ __align__(16) __half g_xh[NN * DD];     // x * cs, fp16
__device__ __align__(16) __half g_h0[NN * DD];     // layer outputs (fp16)
__device__ __align__(16) __half g_h1[NN * DD];
__device__ __align__(16) __half g_h2[NN * DD];
__device__ __align__(16) __half g_agg[NN * DD];    // gathered+cd-scaled rows (fp16)
__device__ __align__(16) __half g_wt[3 * DD * DD]; // W transposed + fp16: wt[l][n][k]
__device__ int   g_degout[NN];
__device__ int   g_degin[NN];
__device__ int   g_rowstart[NN];
__device__ int   g_cursor[NN];                     // seeded to rowstart; atomic bump = slot
__device__ int   g_csr[1700000];
__device__ __align__(16) float g_sums[GG * DD];
__device__ float g_cnt[GG];

// ---------------------------------------------------------------------------
__global__ void count_deg_kernel(const int* __restrict__ src,
                                 const int* __restrict__ dst, int e) {
    int i = blockIdx.x * blockDim.x + threadIdx.x;
    if (i < e) {
        atomicAdd(&g_degout[src[i]], 1);
        atomicAdd(&g_degin[dst[i]], 1);
    }
}

// Single-CTA int-only scan over degin -> rowstart (+cursor=rowstart).
// Norms (rsqrt) are computed inline at each use site, NOT here.
__global__ void scan_kernel(int n) {
    __shared__ int s[1024];
    int t = threadIdx.x;
    int chunk = (n + 1023) >> 10;
    int lo = min(t * chunk, n), hi = min(lo + chunk, n);
    int sum = 0;
    for (int i = lo; i < hi; i++) sum += g_degin[i];
    s[t] = sum;
    __syncthreads();
#pragma unroll
    for (int off = 1; off < 1024; off <<= 1) {
        int add = (t >= off) ? s[t - off] : 0;
        __syncthreads();
        s[t] += add;
        __syncthreads();
    }
    int run = s[t] - sum;   // exclusive
    for (int i = lo; i < hi; i++) {
        g_rowstart[i] = run;
        g_cursor[i] = run;           // cursor doubles as the write position
        run += g_degin[i];
    }
}

// Fused: CSR fill (i < e) + xh prep with inline cs (i < n*32) + W fp16 prep
__global__ void fill_prep_kernel(const int* __restrict__ src,
                                 const int* __restrict__ dst,
                                 const float* __restrict__ x,
                                 const float* __restrict__ W0,
                                 const float* __restrict__ W1,
                                 const float* __restrict__ W2, int e, int n) {
    int i = blockIdx.x * blockDim.x + threadIdx.x;
    if (i < e) {
        int pos = atomicAdd(&g_cursor[dst[i]], 1);
        g_csr[pos] = src[i];
    }
    if (i < n * 32) {
        int node = i >> 5, q = i & 31;
        float c = rsqrtf((float)(__ldg(&g_degout[node]) + 1));   // cs inline
        float4 v = __ldg((const float4*)x + (size_t)node * 32 + q);
        uint2 o;
        *(__half2*)&o.x = __float22half2_rn(make_float2(v.x * c, v.y * c));
        *(__half2*)&o.y = __float22half2_rn(make_float2(v.z * c, v.w * c));
        ((uint2*)g_xh)[(size_t)node * 32 + q] = o;
    }
    if (i < 3 * DD * DD) {
        const float* W = (i < DD * DD) ? W0 : ((i < 2 * DD * DD) ? W1 : W2);
        int j = i & (DD * DD - 1);
        int k = j >> 7, nn = j & 127;
        g_wt[(i >> 14) * DD * DD + nn * DD + k] = __float2half(W[j]);
    }
}

// ---------------------------------------------------------------------------
// Gather: agg[node] = half( cd[node] * ( hs[node] + sum_in hs[src] ) )
// ISSUE-BOUND: one uint2 LDG per edge (1 issue slot; the 2nd cache line is a
// within-LDG wavefront replay, which costs L1tex slots (at ~42%) not SM issue
// slots (at ~51%)) + fp16 tree pre-reduction over 4-edge groups (__hadd2),
// fp32 master accumulator. ~36 instr per 8 edges vs 52 in round 16.
// ---------------------------------------------------------------------------
__global__ void __launch_bounds__(256)
gather_kernel(const __half* __restrict__ h, int n) {
    int w = (blockIdx.x * blockDim.x + threadIdx.x) >> 5;
    int lane = threadIdx.x & 31;
    if (w >= n) return;
    int node = w;
    int base = g_rowstart[node];
    int deg  = g_degin[node];

    uint2 sv = __ldg((const uint2*)h + (size_t)node * 32 + lane);
    float2 f0 = __half22float2(*(__half2*)&sv.x);
    float2 f1 = __half22float2(*(__half2*)&sv.y);
    float4 acc = make_float4(f0.x, f0.y, f1.x, f1.y);

    for (int j0 = 0; j0 < deg; j0 += 32) {
        int cnt = min(32, deg - j0);
        int sj = (lane < cnt) ? __ldg(&g_csr[base + j0 + lane]) : 0;
        int k = 0;
        for (; k + 8 <= cnt; k += 8) {
            int s[8];
#pragma unroll
            for (int u = 0; u < 8; u++) s[u] = __shfl_sync(0xffffffffu, sj, k + u);
            uint2 v[8];
#pragma unroll
            for (int u = 0; u < 8; u++)
                v[u] = __ldg((const uint2*)h + (size_t)s[u] * 32 + lane);
            // fp16 tree reduction over 4-edge groups, then fp32 accumulate
            __half2 p0 = __hadd2(__hadd2(*(__half2*)&v[0].x, *(__half2*)&v[1].x),
                                 __hadd2(*(__half2*)&v[2].x, *(__half2*)&v[3].x));
            __half2 p1 = __hadd2(__hadd2(*(__half2*)&v[4].x, *(__half2*)&v[5].x),
                                 __hadd2(*(__half2*)&v[6].x, *(__half2*)&v[7].x));
            __half2 q0 = __hadd2(__hadd2(*(__half2*)&v[0].y, *(__half2*)&v[1].y),
                                 __hadd2(*(__half2*)&v[2].y, *(__half2*)&v[3].y));
            __half2 q1 = __hadd2(__hadd2(*(__half2*)&v[4].y, *(__half2*)&v[5].y),
                                 __hadd2(*(__half2*)&v[6].y, *(__half2*)&v[7].y));
            float2 f;
            f = __half22float2(p0); acc.x += f.x; acc.y += f.y;
            f = __half22float2(p1); acc.x += f.x; acc.y += f.y;
            f = __half22float2(q0); acc.z += f.x; acc.w += f.y;
            f = __half22float2(q1); acc.z += f.x; acc.w += f.y;
        }
        for (; k < cnt; k++) {
            int s0 = __shfl_sync(0xffffffffu, sj, k);
            uint2 v0 = __ldg((const uint2*)h + (size_t)s0 * 32 + lane);
            float2 b0 = __half22float2(*(__half2*)&v0.x);
            float2 b1 = __half22float2(*(__half2*)&v0.y);
            acc.x += b0.x; acc.y += b0.y; acc.z += b1.x; acc.w += b1.y;
        }
    }

    float cdv = rsqrtf((float)(deg + 1));   // cd inline (deg already loaded)
    uint2 o;
    *(__half2*)&o.x = __float22half2_rn(make_float2(acc.x * cdv, acc.y * cdv));
    *(__half2*)&o.y = __float22half2_rn(make_float2(acc.z * cdv, acc.w * cdv));
    ((uint2*)g_agg)[(size_t)node * 32 + lane] = o;
}

// ---------------------------------------------------------------------------
// Tensor-core GEMM, fp16 inputs / fp32 accum (mma.sync m16n8k16).
// out = half( relu(agg @ W + b) [* cs[row]] ), cs computed inline from degout.
// One CTA per 128 rows, 8 warps each 32(M)x64(N). Smem stride 136 halfs.
// ---------------------------------------------------------------------------
#define ASTR 136
#define GT_SMEM (2 * 128 * ASTR * 2)

__global__ void __launch_bounds__(256, 1)
gemm_mma_kernel(const __half* __restrict__ wt, const float* __restrict__ b,
                __half* __restrict__ out, int n, int cs_out) {
    extern __shared__ __half sh[];
    __half* Bsm = sh;               // 128 x ASTR : Wt[n][k]
    __half* Asm = sh + 128 * ASTR;  // 128 x ASTR : A[m][k]

    int t = threadIdx.x;
    int rows0 = blockIdx.x * 128;

#pragma unroll
    for (int it = 0; it < 8; it++) {
        int idx = t + it * 256;
        int r = idx >> 4, c = idx & 15;
        *(uint4*)&Bsm[r * ASTR + c * 8] = __ldg((const uint4*)wt + idx);
    }
#pragma unroll
    for (int it = 0; it < 8; it++) {
        int idx = t + it * 256;
        int r = idx >> 4, c = idx & 15;
        int gr = rows0 + r;
        if (gr > n - 1) gr = n - 1;
        *(uint4*)&Asm[r * ASTR + c * 8] = __ldg((const uint4*)(g_agg + (size_t)gr * DD) + c);
    }
    __syncthreads();

    int wid = t >> 5, lane = t & 31;
    int groupID = lane >> 2, ktid = lane & 3;
    int warpM = (wid & 3) * 32;
    int warpN = (wid >> 2) * 64;

    float acc[2][8][4];
#pragma unroll
    for (int mt = 0; mt < 2; mt++)
#pragma unroll
        for (int nt = 0; nt < 8; nt++)
#pragma unroll
            for (int q = 0; q < 4; q++) acc[mt][nt][q] = 0.0f;

#pragma unroll
    for (int k0 = 0; k0 < 128; k0 += 16) {
        uint32_t a[2][4];
#pragma unroll
        for (int mt = 0; mt < 2; mt++) {
            int r0 = warpM + mt * 16 + groupID;
            a[mt][0] = *(const uint32_t*)&Asm[r0 * ASTR + k0 + ktid * 2];
            a[mt][1] = *(const uint32_t*)&Asm[(r0 + 8) * ASTR + k0 + ktid * 2];
            a[mt][2] = *(const uint32_t*)&Asm[r0 * ASTR + k0 + ktid * 2 + 8];
            a[mt][3] = *(const uint32_t*)&Asm[(r0 + 8) * ASTR + k0 + ktid * 2 + 8];
        }
#pragma unroll
        for (int nt = 0; nt < 8; nt++) {
            int c0 = warpN + nt * 8 + groupID;
            uint32_t b0 = *(const uint32_t*)&Bsm[c0 * ASTR + k0 + ktid * 2];
            uint32_t b1 = *(const uint32_t*)&Bsm[c0 * ASTR + k0 + ktid * 2 + 8];
#pragma unroll
            for (int mt = 0; mt < 2; mt++) {
                asm volatile(
                    "mma.sync.aligned.m16n8k16.row.col.f32.f16.f16.f32 "
                    "{%0,%1,%2,%3}, {%4,%5,%6,%7}, {%8,%9}, {%0,%1,%2,%3};"
                    : "+f"(acc[mt][nt][0]), "+f"(acc[mt][nt][1]),
                      "+f"(acc[mt][nt][2]), "+f"(acc[mt][nt][3])
                    : "r"(a[mt][0]), "r"(a[mt][1]), "r"(a[mt][2]), "r"(a[mt][3]),
                      "r"(b0), "r"(b1));
            }
        }
    }

#pragma unroll
    for (int mt = 0; mt < 2; mt++) {
        int r0 = rows0 + warpM + mt * 16 + groupID;
        int r1 = r0 + 8;
        float sc0 = 1.0f, sc1 = 1.0f;
        if (cs_out) {
            if (r0 < n) sc0 = rsqrtf((float)(__ldg(&g_degout[r0]) + 1));
            if (r1 < n) sc1 = rsqrtf((float)(__ldg(&g_degout[r1]) + 1));
        }
#pragma unroll
        for (int nt = 0; nt < 8; nt++) {
            int col = warpN + nt * 8 + 2 * ktid;
            float2 bb = __ldg((const float2*)(b + col));
            if (r0 < n) {
                float2 o = make_float2(fmaxf(acc[mt][nt][0] + bb.x, 0.0f) * sc0,
                                       fmaxf(acc[mt][nt][1] + bb.y, 0.0f) * sc0);
                *(__half2*)(out + (size_t)r0 * DD + col) = __float22half2_rn(o);
            }
            if (r1 < n) {
                float2 o = make_float2(fmaxf(acc[mt][nt][2] + bb.x, 0.0f) * sc1,
                                       fmaxf(acc[mt][nt][3] + bb.y, 0.0f) * sc1);
                *(__half2*)(out + (size_t)r1 * DD + col) = __float22half2_rn(o);
            }
        }
    }
}

// ---------------------------------------------------------------------------
// Pooling: graph_ids sorted -> run-based accumulation, flush per run.
// ---------------------------------------------------------------------------
__global__ void pool_kernel(const __half* __restrict__ h,
                            const int* __restrict__ gid, int n) {
    int w = (blockIdx.x * blockDim.x + threadIdx.x) >> 5;
    int lane = threadIdx.x & 31;
    int n0 = w * 16;
    if (n0 >= n) return;
    int n1 = min(n0 + 16, n);

    float4 acc = make_float4(0.f, 0.f, 0.f, 0.f);
    int curg = gid[n0];
    int cnt = 0;
    for (int node = n0; node < n1; node++) {
        int g = gid[node];
        if (g != curg) {
            float* o = g_sums + curg * DD + lane * 4;
            asm volatile("red.global.add.v4.f32 [%0], {%1, %2, %3, %4};"
                         :: "l"(o), "f"(acc.x), "f"(acc.y), "f"(acc.z), "f"(acc.w)
                         : "memory");
            if (lane == 0) atomicAdd(&g_cnt[curg], (float)cnt);
            acc = make_float4(0.f, 0.f, 0.f, 0.f);
            curg = g; cnt = 0;
        }
        uint2 v = __ldg((const uint2*)h + (size_t)node * 32 + lane);
        float2 a0 = __half22float2(*(__half2*)&v.x);
        float2 a1 = __half22float2(*(__half2*)&v.y);
        acc.x += a0.x; acc.y += a0.y; acc.z += a1.x; acc.w += a1.y;
        cnt++;
    }
    float* o = g_sums + curg * DD + lane * 4;
    asm volatile("red.global.add.v4.f32 [%0], {%1, %2, %3, %4};"
                 :: "l"(o), "f"(acc.x), "f"(acc.y), "f"(acc.z), "f"(acc.w)
                 : "memory");
    if (lane == 0) atomicAdd(&g_cnt[curg], (float)cnt);
}

__global__ void divide_kernel(float* __restrict__ out) {
    int i = blockIdx.x * blockDim.x + threadIdx.x;
    if (i < GG * DD) out[i] = g_sums[i] / fmaxf(g_cnt[i >> 7], 1.0f);
}

// ---------------------------------------------------------------------------
extern "C" void kernel_launch(void* const* d_in, const int* in_sizes, int n_in,
                              void* d_out, int out_size) {
    const float* x  = (const float*)d_in[0];
    const float* Ws[3] = {(const float*)d_in[1], (const float*)d_in[3], (const float*)d_in[5]};
    const float* bs[3] = {(const float*)d_in[2], (const float*)d_in[4], (const float*)d_in[6]};
    const int* src = (const int*)d_in[7];
    const int* dst = (const int*)d_in[8];
    const int* gid = (const int*)d_in[9];

    int n = in_sizes[0] / DD;          // 100000
    int e = in_sizes[7];               // 1600000

    cudaFuncSetAttribute(gemm_mma_kernel,
                         cudaFuncAttributeMaxDynamicSharedMemorySize, GT_SMEM);

    void* pxh; cudaGetSymbolAddress(&pxh, g_xh);
    void* p0;  cudaGetSymbolAddress(&p0, g_h0);
    void* p1;  cudaGetSymbolAddress(&p1, g_h1);
    void* p2;  cudaGetSymbolAddress(&p2, g_h2);
    void* pw;  cudaGetSymbolAddress(&pw, g_wt);
    void* pdo; cudaGetSymbolAddress(&pdo, g_degout);
    void* pdi; cudaGetSymbolAddress(&pdi, g_degin);
    void* psu; cudaGetSymbolAddress(&psu, g_sums);
    void* pcn; cudaGetSymbolAddress(&pcn, g_cnt);
    __half* xh = (__half*)pxh;
    __half* h0 = (__half*)p0;
    __half* h1 = (__half*)p1;
    __half* h2 = (__half*)p2;
    __half* wt = (__half*)pw;

    // Zeroing via memset nodes (not kernel launches)
    cudaMemsetAsync(pdo, 0, (size_t)n * sizeof(int));
    cudaMemsetAsync(pdi, 0, (size_t)n * sizeof(int));
    cudaMemsetAsync(psu, 0, GG * DD * sizeof(float));
    cudaMemsetAsync(pcn, 0, GG * sizeof(float));

    int gtiles = (n + 127) / 128;
    int gblocks = (int)(((size_t)n * 32 + 255) / 256);

    count_deg_kernel<<<(e + 255) / 256, 256>>>(src, dst, e);                 // launch 1
    scan_kernel<<<1, 1024>>>(n);                                             // launch 2
    fill_prep_kernel<<<(int)(((size_t)n * 32 + 255) / 256), 256>>>(
        src, dst, x, Ws[0], Ws[1], Ws[2], e, n);                             // launch 3
    gather_kernel<<<gblocks, 256>>>(xh, n);                                  // launch 4 (profiled)
    gemm_mma_kernel<<<gtiles, 256, GT_SMEM>>>(wt, bs[0], h0, n, 1);
    gather_kernel<<<gblocks, 256>>>(h0, n);
    gemm_mma_kernel<<<gtiles, 256, GT_SMEM>>>(wt + DD * DD, bs[1], h1, n, 1);
    gather_kernel<<<gblocks, 256>>>(h1, n);
    gemm_mma_kernel<<<gtiles, 256, GT_SMEM>>>(wt + 2 * DD * DD, bs[2], h2, n, 0);

    pool_kernel<<<(n + 127) / 128, 256>>>(h2, gid, n);
    divide_kernel<<<(GG * DD + 255) / 256, 256>>>((float*)d_out);
}